// round 1
// baseline (speedup 1.0000x reference)
#include <cuda_runtime.h>

// Problem constants
#define TB   4
#define TT   2048
#define TD   1024
#define TH   16
#define TDH  64
#define NTOK (TB * TT)          // 8192

// ---------------------------------------------------------------------------
// Scratch (device globals: allocation-free, graph-capture safe)
// ---------------------------------------------------------------------------
__device__ float g_q[TB * TH * TT * TDH];     // [b][h][t][dh]  32 MB
__device__ float g_k[TB * TH * TT * TDH];
__device__ float g_v[TB * TH * TT * TDH];
__device__ float g_attn[NTOK * TD];           // [n][d] row-major 32 MB

// ---------------------------------------------------------------------------
// GEMM with fused bias:  C[m][n] = sum_k A[m][k] * W[n][k] + bias[n]
// A: [M=8192, K=1024] row-major, W: [N=1024, K=1024] row-major.
// 128x128 tile, TK=8, 256 threads, 8x8 per thread, double-buffered smem.
// mode 0: scatter to [b][h][t][dh] layout; mode 1: row-major [m][n].
// ---------------------------------------------------------------------------
__global__ __launch_bounds__(256, 2) void gemm_bias(
    const float* __restrict__ A, const float* __restrict__ W,
    const float* __restrict__ bias, float* __restrict__ Cout, int mode)
{
    __shared__ float As[2][8][128];   // [buf][k][m]
    __shared__ float Bs[2][8][128];   // [buf][k][n]

    const int tid   = threadIdx.x;
    const int tx    = tid & 15;       // n-direction
    const int ty    = tid >> 4;       // m-direction
    const int mbase = blockIdx.y * 128;
    const int nbase = blockIdx.x * 128;

    // loader mapping: 256 threads cover 128 rows x 2 float4 (k0..3 / k4..7)
    const int lr = tid >> 1;
    const int lk = (tid & 1) * 4;
    const float* Ag = A + (size_t)(mbase + lr) * TD + lk;
    const float* Wg = W + (size_t)(nbase + lr) * TD + lk;

    float acc[8][8];
    #pragma unroll
    for (int i = 0; i < 8; i++)
        #pragma unroll
        for (int j = 0; j < 8; j++) acc[i][j] = 0.0f;

    float4 ra = *(const float4*)Ag;
    float4 rb = *(const float4*)Wg;
    As[0][lk + 0][lr] = ra.x; As[0][lk + 1][lr] = ra.y;
    As[0][lk + 2][lr] = ra.z; As[0][lk + 3][lr] = ra.w;
    Bs[0][lk + 0][lr] = rb.x; Bs[0][lk + 1][lr] = rb.y;
    Bs[0][lk + 2][lr] = rb.z; Bs[0][lk + 3][lr] = rb.w;
    __syncthreads();

    int buf = 0;
    for (int kt = 1; kt <= TD / 8; kt++) {
        if (kt < TD / 8) {
            ra = *(const float4*)(Ag + kt * 8);
            rb = *(const float4*)(Wg + kt * 8);
        }
        #pragma unroll
        for (int kk = 0; kk < 8; kk++) {
            float4 a0 = *(const float4*)&As[buf][kk][ty * 8];
            float4 a1 = *(const float4*)&As[buf][kk][ty * 8 + 4];
            float4 b0 = *(const float4*)&Bs[buf][kk][tx * 8];
            float4 b1 = *(const float4*)&Bs[buf][kk][tx * 8 + 4];
            float av[8] = {a0.x, a0.y, a0.z, a0.w, a1.x, a1.y, a1.z, a1.w};
            float bv[8] = {b0.x, b0.y, b0.z, b0.w, b1.x, b1.y, b1.z, b1.w};
            #pragma unroll
            for (int i = 0; i < 8; i++)
                #pragma unroll
                for (int j = 0; j < 8; j++)
                    acc[i][j] += av[i] * bv[j];
        }
        if (kt < TD / 8) {
            int nb = buf ^ 1;
            As[nb][lk + 0][lr] = ra.x; As[nb][lk + 1][lr] = ra.y;
            As[nb][lk + 2][lr] = ra.z; As[nb][lk + 3][lr] = ra.w;
            Bs[nb][lk + 0][lr] = rb.x; Bs[nb][lk + 1][lr] = rb.y;
            Bs[nb][lk + 2][lr] = rb.z; Bs[nb][lk + 3][lr] = rb.w;
            buf = nb;
        }
        __syncthreads();
    }

    // epilogue: bias + write
    float bv[8];
    #pragma unroll
    for (int j = 0; j < 8; j++) bv[j] = bias[nbase + tx * 8 + j];

    if (mode == 0) {
        // scatter into [b][h][t][dh]
        #pragma unroll
        for (int i = 0; i < 8; i++) {
            int mrow = mbase + ty * 8 + i;
            int b = mrow >> 11;           // / 2048
            int t = mrow & (TT - 1);
            // a thread's 8 columns never cross a 64-wide head boundary
            int col0 = nbase + tx * 8;
            int h    = col0 >> 6;
            int dh0  = col0 & 63;
            float* op = g_q; // placeholder, overwritten below via Cout
            op = Cout;
            size_t base = (((size_t)(b * TH + h)) * TT + t) * TDH + dh0;
            #pragma unroll
            for (int j = 0; j < 8; j++)
                op[base + j] = acc[i][j] + bv[j];
        }
    } else {
        #pragma unroll
        for (int i = 0; i < 8; i++) {
            int mrow = mbase + ty * 8 + i;
            size_t base = (size_t)mrow * TD + nbase + tx * 8;
            #pragma unroll
            for (int j = 0; j < 8; j++)
                Cout[base + j] = acc[i][j] + bv[j];
        }
    }
}

// ---------------------------------------------------------------------------
// Flash attention (fp32). One block = one (b*H + h, 64-query tile).
// 256 threads; thread (r = tid/16, c = tid&15) owns a 4x4 microtile.
// Q,K stored dim-major [dh][t] stride 65; V row-major [t][dh]; P transposed.
// ---------------------------------------------------------------------------
#define QK_STRIDE 65
#define ATTN_SMEM_FLOATS (64 * QK_STRIDE * 3 + 64 * 64)

__global__ __launch_bounds__(256) void attn_kernel(
    const float* __restrict__ Q, const float* __restrict__ Kg_,
    const float* __restrict__ Vg_, float* __restrict__ Out)
{
    extern __shared__ float sm[];
    float* Qs = sm;                         // [64][65] dim-major
    float* Ks = Qs + 64 * QK_STRIDE;        // [64][65] dim-major
    float* Ps = Ks + 64 * QK_STRIDE;        // [64][65]  P transposed: [j][i]
    float* Vs = Ps + 64 * QK_STRIDE;        // [64][64] row-major [t][dh]

    const int tid = threadIdx.x;
    const int c = tid & 15;   // S column group (key dir / output dh dir)
    const int r = tid >> 4;   // S row group (query dir)
    const int bh = blockIdx.y;            // b*16 + h
    const int q0 = blockIdx.x * 64;

    const float* Qp = Q   + (size_t)bh * TT * TDH;
    const float* Kp = Kg_ + (size_t)bh * TT * TDH;
    const float* Vp = Vg_ + (size_t)bh * TT * TDH;

    // Load Q tile (transposed to dim-major)
    for (int idx = tid; idx < 64 * 64; idx += 256) {
        int t = idx >> 6, dh = idx & 63;
        Qs[dh * QK_STRIDE + t] = Qp[(size_t)(q0 + t) * TDH + dh];
    }

    float mrow[4], lrow[4], o[4][4];
    #pragma unroll
    for (int i = 0; i < 4; i++) {
        mrow[i] = -1e30f; lrow[i] = 0.0f;
        #pragma unroll
        for (int j = 0; j < 4; j++) o[i][j] = 0.0f;
    }

    for (int kt = 0; kt < TT; kt += 64) {
        __syncthreads();  // previous O-accum done (and Q load on first iter pairs with next sync)
        for (int idx = tid; idx < 64 * 64; idx += 256) {
            int t = idx >> 6, dh = idx & 63;
            float kvval = Kp[(size_t)(kt + t) * TDH + dh];
            Ks[dh * QK_STRIDE + t] = kvval;
            Vs[t * 64 + dh] = Vp[(size_t)(kt + t) * TDH + dh];
        }
        __syncthreads();

        // S = Q K^T (4x4 per thread), scaled
        float s[4][4];
        #pragma unroll
        for (int i = 0; i < 4; i++)
            #pragma unroll
            for (int j = 0; j < 4; j++) s[i][j] = 0.0f;

        #pragma unroll 8
        for (int kk = 0; kk < 64; kk++) {
            float qf[4], kf[4];
            #pragma unroll
            for (int ii = 0; ii < 4; ii++) qf[ii] = Qs[kk * QK_STRIDE + r * 4 + ii];
            #pragma unroll
            for (int jj = 0; jj < 4; jj++) kf[jj] = Ks[kk * QK_STRIDE + c * 4 + jj];
            #pragma unroll
            for (int ii = 0; ii < 4; ii++)
                #pragma unroll
                for (int jj = 0; jj < 4; jj++)
                    s[ii][jj] += qf[ii] * kf[jj];
        }

        // online softmax update
        #pragma unroll
        for (int ii = 0; ii < 4; ii++) {
            float tm = -1e30f;
            #pragma unroll
            for (int jj = 0; jj < 4; jj++) {
                s[ii][jj] *= 0.125f;
                tm = fmaxf(tm, s[ii][jj]);
            }
            #pragma unroll
            for (int off = 8; off > 0; off >>= 1)
                tm = fmaxf(tm, __shfl_xor_sync(0xffffffffu, tm, off));
            float mn = fmaxf(mrow[ii], tm);
            float al = __expf(mrow[ii] - mn);
            float rs = 0.0f;
            #pragma unroll
            for (int jj = 0; jj < 4; jj++) {
                float p = __expf(s[ii][jj] - mn);
                s[ii][jj] = p;
                rs += p;
            }
            #pragma unroll
            for (int off = 8; off > 0; off >>= 1)
                rs += __shfl_xor_sync(0xffffffffu, rs, off);
            lrow[ii] = lrow[ii] * al + rs;
            mrow[ii] = mn;
            #pragma unroll
            for (int jj = 0; jj < 4; jj++) o[ii][jj] *= al;
        }

        // stage P transposed: Ps[j][i]
        #pragma unroll
        for (int ii = 0; ii < 4; ii++)
            #pragma unroll
            for (int jj = 0; jj < 4; jj++)
                Ps[(c * 4 + jj) * QK_STRIDE + r * 4 + ii] = s[ii][jj];
        __syncthreads();

        // O += P V
        #pragma unroll 8
        for (int j = 0; j < 64; j++) {
            float pf[4];
            #pragma unroll
            for (int ii = 0; ii < 4; ii++) pf[ii] = Ps[j * QK_STRIDE + r * 4 + ii];
            float4 vv = *(const float4*)&Vs[j * 64 + c * 4];
            #pragma unroll
            for (int ii = 0; ii < 4; ii++) {
                o[ii][0] += pf[ii] * vv.x;
                o[ii][1] += pf[ii] * vv.y;
                o[ii][2] += pf[ii] * vv.z;
                o[ii][3] += pf[ii] * vv.w;
            }
        }
    }

    // write normalized output into [n][d] row-major scratch
    const int b = bh >> 4;
    const int h = bh & 15;
    #pragma unroll
    for (int ii = 0; ii < 4; ii++) {
        float inv = 1.0f / lrow[ii];
        int t = q0 + r * 4 + ii;
        size_t n = (size_t)b * TT + t;
        float* op = Out + n * TD + h * TDH + c * 4;
        op[0] = o[ii][0] * inv;
        op[1] = o[ii][1] * inv;
        op[2] = o[ii][2] * inv;
        op[3] = o[ii][3] * inv;
    }
}

// ---------------------------------------------------------------------------
// Launch
// ---------------------------------------------------------------------------
extern "C" void kernel_launch(void* const* d_in, const int* in_sizes, int n_in,
                              void* d_out, int out_size)
{
    const float* query = (const float*)d_in[0];
    const float* key   = (const float*)d_in[1];
    const float* value = (const float*)d_in[2];
    const float* w_q   = (const float*)d_in[3];
    const float* b_q   = (const float*)d_in[4];
    const float* w_k   = (const float*)d_in[5];
    const float* b_k   = (const float*)d_in[6];
    const float* w_v   = (const float*)d_in[7];
    const float* b_v   = (const float*)d_in[8];
    const float* w_o   = (const float*)d_in[9];
    const float* b_o   = (const float*)d_in[10];
    float* out = (float*)d_out;

    float *qp, *kp, *vp, *ap;
    cudaGetSymbolAddress((void**)&qp, g_q);
    cudaGetSymbolAddress((void**)&kp, g_k);
    cudaGetSymbolAddress((void**)&vp, g_v);
    cudaGetSymbolAddress((void**)&ap, g_attn);

    dim3 gg(TD / 128, NTOK / 128);   // (8, 64)
    dim3 gb(256);
    gemm_bias<<<gg, gb>>>(query, w_q, b_q, qp, 0);
    gemm_bias<<<gg, gb>>>(key,   w_k, b_k, kp, 0);
    gemm_bias<<<gg, gb>>>(value, w_v, b_v, vp, 0);

    int smem = ATTN_SMEM_FLOATS * (int)sizeof(float);   // ~66 KB
    cudaFuncSetAttribute(attn_kernel, cudaFuncAttributeMaxDynamicSharedMemorySize, smem);
    attn_kernel<<<dim3(TT / 64, TB * TH), 256, smem>>>(qp, kp, vp, ap);

    gemm_bias<<<gg, gb>>>(ap, w_o, b_o, out, 1);
}

// round 3
// speedup vs baseline: 1.4929x; 1.4929x over previous
#include <cuda_runtime.h>
#include <cuda_bf16.h>
#include <cstdint>

// Problem constants
#define TB   4
#define TT   2048
#define TD   1024
#define TH   16
#define TDH  64
#define NTOK (TB * TT)          // 8192

// ---------------------------------------------------------------------------
// Scratch (device globals: allocation-free, graph-capture safe)
// ---------------------------------------------------------------------------
__device__ float g_q[TB * TH * TT * TDH];     // [b][h][t][dh]
__device__ float g_k[TB * TH * TT * TDH];
__device__ float g_v[TB * TH * TT * TDH];
__device__ float g_attn[NTOK * TD];           // [n][d] row-major

// ---------------------------------------------------------------------------
// mma.sync helpers (compute_100-safe: sm_80+ features only)
// ---------------------------------------------------------------------------
__device__ __forceinline__ uint32_t smem_u32(const void* p) {
    uint32_t a;
    asm("{ .reg .u64 t; cvta.to.shared.u64 t, %1; cvt.u32.u64 %0, t; }"
        : "=r"(a) : "l"(p));
    return a;
}

#define LDMX4(r, addr) \
    asm volatile("ldmatrix.sync.aligned.m8n8.x4.shared.b16 {%0,%1,%2,%3}, [%4];" \
        : "=r"((r)[0]), "=r"((r)[1]), "=r"((r)[2]), "=r"((r)[3]) : "r"(addr))

#define MMA16816(d, a, b) \
    asm volatile("mma.sync.aligned.m16n8k16.row.col.f32.bf16.bf16.f32 " \
        "{%0,%1,%2,%3}, {%4,%5,%6,%7}, {%8,%9}, {%0,%1,%2,%3};" \
        : "+f"((d)[0]), "+f"((d)[1]), "+f"((d)[2]), "+f"((d)[3]) \
        : "r"((a)[0]), "r"((a)[1]), "r"((a)[2]), "r"((a)[3]), \
          "r"((b)[0]), "r"((b)[1]))

// split fp32 pair into packed bf16 hi / lo pairs (x -> low half)
__device__ __forceinline__ void split2(float x, float y, uint32_t& hi, uint32_t& lo) {
    __nv_bfloat16 hx = __float2bfloat16(x);
    __nv_bfloat16 hy = __float2bfloat16(y);
    float lx = x - __bfloat162float(hx);
    float ly = y - __bfloat162float(hy);
    __nv_bfloat162 H; H.x = hx; H.y = hy;
    __nv_bfloat162 L; L.x = __float2bfloat16(lx); L.y = __float2bfloat16(ly);
    hi = *reinterpret_cast<uint32_t*>(&H);
    lo = *reinterpret_cast<uint32_t*>(&L);
}

// ---------------------------------------------------------------------------
// Tensor-core GEMM with fused bias (bf16x3 split, fp32-accurate):
//   C[m][n] = sum_k A[m][k] * W[n][k] + bias[n]
// CTA 128x128, BK=32, 256 threads (8 warps: 4M x 2N, warp tile 32x64).
// Tiles in smem: [row][k] k-contiguous, stride 40 bf16 (conflict-free ldmatrix).
// mode 0: scatter to [b][h][t][dh]; mode 1: row-major [m][n].
// ---------------------------------------------------------------------------
#define BK 32
#define TSTRIDE 40                        // bf16 elems per smem row
#define TILE_U16 (128 * TSTRIDE)          // 5120 uint16 per tile
#define TILE_BYTES (TILE_U16 * 2)         // 10240
#define STAGE_BYTES (4 * TILE_BYTES)      // A_hi, A_lo, B_hi, B_lo
#define GEMM_SMEM (2 * STAGE_BYTES)       // 81920

__global__ __launch_bounds__(256, 2) void gemm_tc(
    const float* __restrict__ A, const float* __restrict__ W,
    const float* __restrict__ bias, float* __restrict__ Cout, int mode)
{
    extern __shared__ char smem[];
    const uint32_t sbase = smem_u32(smem);
    const int tid  = threadIdx.x;
    const int lane = tid & 31;
    const int wid  = tid >> 5;
    const int warp_m = wid & 3;       // 4 warps along M, 32 rows each
    const int warp_n = wid >> 2;      // 2 warps along N, 64 cols each
    const int mbase = blockIdx.y * 128;
    const int nbase = blockIdx.x * 128;

    // loader mapping: 256 threads; thread covers rows lrow+32i (i=0..3), 4 floats at lkq
    const int lrow = tid >> 3;        // 0..31
    const int lkq  = (tid & 7) * 4;   // 0,4,...,28

    // per-lane ldmatrix address components
    const int a_mi   = lane >> 3;
    const int a_roff = ((a_mi & 1) << 3) + (lane & 7);
    const int a_koff = (a_mi >> 1) << 3;
    const int b_roff = (((lane >> 4) & 1) << 3) + (lane & 7);
    const int b_koff = ((lane >> 3) & 1) << 3;

    float4 va[4], vb[4];

    auto LOAD = [&](int cc) {
        const float* ap = A + (size_t)(mbase + lrow) * TD + cc * BK + lkq;
        const float* wp = W + (size_t)(nbase + lrow) * TD + cc * BK + lkq;
        #pragma unroll
        for (int i = 0; i < 4; i++) va[i] = *(const float4*)(ap + (size_t)(32 * i) * TD);
        #pragma unroll
        for (int i = 0; i < 4; i++) vb[i] = *(const float4*)(wp + (size_t)(32 * i) * TD);
    };

    auto STORE = [&](int s) {
        uint16_t* base = (uint16_t*)(smem + s * STAGE_BYTES);
        #pragma unroll
        for (int i = 0; i < 4; i++) {
            int off = (lrow + 32 * i) * TSTRIDE + lkq;
            uint32_t h0, l0, h1, l1;
            split2(va[i].x, va[i].y, h0, l0);
            split2(va[i].z, va[i].w, h1, l1);
            *(uint2*)(base + off)            = make_uint2(h0, h1);
            *(uint2*)(base + TILE_U16 + off) = make_uint2(l0, l1);
            split2(vb[i].x, vb[i].y, h0, l0);
            split2(vb[i].z, vb[i].w, h1, l1);
            *(uint2*)(base + 2 * TILE_U16 + off) = make_uint2(h0, h1);
            *(uint2*)(base + 3 * TILE_U16 + off) = make_uint2(l0, l1);
        }
    };

    float acc[2][8][4];
    #pragma unroll
    for (int mt = 0; mt < 2; mt++)
        #pragma unroll
        for (int nt = 0; nt < 8; nt++)
            #pragma unroll
            for (int r = 0; r < 4; r++) acc[mt][nt][r] = 0.0f;

    LOAD(0);
    STORE(0);
    __syncthreads();

    for (int c = 0; c < TD / BK; c++) {
        if (c < TD / BK - 1) LOAD(c + 1);

        const uint32_t sa = sbase + (c & 1) * STAGE_BYTES;           // A_hi
        const uint32_t sb = sa + 2 * TILE_BYTES;                      // B_hi

        #pragma unroll
        for (int ks = 0; ks < 2; ks++) {
            const int k0 = ks * 16;
            uint32_t a_hi[2][4], a_lo[2][4];
            #pragma unroll
            for (int mt = 0; mt < 2; mt++) {
                int row = warp_m * 32 + mt * 16 + a_roff;
                uint32_t ad = sa + (uint32_t)(row * TSTRIDE + k0 + a_koff) * 2;
                LDMX4(a_hi[mt], ad);
                LDMX4(a_lo[mt], ad + TILE_BYTES);
            }
            #pragma unroll
            for (int ntp = 0; ntp < 4; ntp++) {
                int row = warp_n * 64 + ntp * 16 + b_roff;
                uint32_t bd = sb + (uint32_t)(row * TSTRIDE + k0 + b_koff) * 2;
                uint32_t bh[4], bl[4];
                LDMX4(bh, bd);
                LDMX4(bl, bd + TILE_BYTES);
                #pragma unroll
                for (int mt = 0; mt < 2; mt++) {
                    MMA16816(acc[mt][ntp * 2],     a_hi[mt], &bh[0]);
                    MMA16816(acc[mt][ntp * 2],     a_hi[mt], &bl[0]);
                    MMA16816(acc[mt][ntp * 2],     a_lo[mt], &bh[0]);
                    MMA16816(acc[mt][ntp * 2 + 1], a_hi[mt], &bh[2]);
                    MMA16816(acc[mt][ntp * 2 + 1], a_hi[mt], &bl[2]);
                    MMA16816(acc[mt][ntp * 2 + 1], a_lo[mt], &bh[2]);
                }
            }
        }
        __syncthreads();
        if (c < TD / BK - 1) {
            STORE((c + 1) & 1);
            __syncthreads();
        }
    }

    // epilogue: bias + store. lane: gid = lane>>2 (row), tig = lane&3 (col pair)
    const int gid = lane >> 2;
    const int tig = lane & 3;
    float2 bb[8];
    #pragma unroll
    for (int nt = 0; nt < 8; nt++)
        bb[nt] = *(const float2*)&bias[nbase + warp_n * 64 + nt * 8 + tig * 2];

    #pragma unroll
    for (int mt = 0; mt < 2; mt++) {
        #pragma unroll
        for (int half = 0; half < 2; half++) {
            int m = mbase + warp_m * 32 + mt * 16 + gid + half * 8;
            if (mode == 0) {
                int b = m >> 11;
                int t = m & (TT - 1);
                int h = (nbase + warp_n * 64) >> 6;
                float* op = Cout + (((size_t)(b * TH + h)) * TT + t) * TDH;
                #pragma unroll
                for (int nt = 0; nt < 8; nt++) {
                    float2 v;
                    v.x = acc[mt][nt][half * 2 + 0] + bb[nt].x;
                    v.y = acc[mt][nt][half * 2 + 1] + bb[nt].y;
                    *(float2*)(op + nt * 8 + tig * 2) = v;
                }
            } else {
                float* op = Cout + (size_t)m * TD + nbase + warp_n * 64;
                #pragma unroll
                for (int nt = 0; nt < 8; nt++) {
                    float2 v;
                    v.x = acc[mt][nt][half * 2 + 0] + bb[nt].x;
                    v.y = acc[mt][nt][half * 2 + 1] + bb[nt].y;
                    *(float2*)(op + nt * 8 + tig * 2) = v;
                }
            }
        }
    }
}

// ---------------------------------------------------------------------------
// Flash attention (fp32). One block = one (b*H + h, 64-query tile).
// 256 threads; thread (r = tid/16, c = tid&15) owns a 4x4 microtile.
// Stride 68 floats (16B aligned) -> vectorized LDS.128/STS.128.
// ---------------------------------------------------------------------------
#define QK_STRIDE 68
#define ATTN_SMEM_FLOATS (64 * QK_STRIDE * 3 + 64 * 64)

__global__ __launch_bounds__(256) void attn_kernel(
    const float* __restrict__ Q, const float* __restrict__ Kg_,
    const float* __restrict__ Vg_, float* __restrict__ Out)
{
    extern __shared__ float sm[];
    float* Qs = sm;                         // [64][68] dim-major
    float* Ks = Qs + 64 * QK_STRIDE;        // [64][68] dim-major
    float* Ps = Ks + 64 * QK_STRIDE;        // [64][68]  P transposed: [j][i]
    float* Vs = Ps + 64 * QK_STRIDE;        // [64][64] row-major [t][dh]

    const int tid = threadIdx.x;
    const int c = tid & 15;   // S column group (key dir / output dh dir)
    const int r = tid >> 4;   // S row group (query dir)
    const int bh = blockIdx.y;            // b*16 + h
    const int q0 = blockIdx.x * 64;

    const float* Qp = Q   + (size_t)bh * TT * TDH;
    const float* Kp = Kg_ + (size_t)bh * TT * TDH;
    const float* Vp = Vg_ + (size_t)bh * TT * TDH;

    // Load Q tile (transposed to dim-major)
    for (int idx = tid; idx < 64 * 64; idx += 256) {
        int t = idx >> 6, dh = idx & 63;
        Qs[dh * QK_STRIDE + t] = Qp[(size_t)(q0 + t) * TDH + dh];
    }

    float mrow[4], lrow[4], o[4][4];
    #pragma unroll
    for (int i = 0; i < 4; i++) {
        mrow[i] = -1e30f; lrow[i] = 0.0f;
        #pragma unroll
        for (int j = 0; j < 4; j++) o[i][j] = 0.0f;
    }

    for (int kt = 0; kt < TT; kt += 64) {
        __syncthreads();
        for (int idx = tid; idx < 64 * 64; idx += 256) {
            int t = idx >> 6, dh = idx & 63;
            Ks[dh * QK_STRIDE + t] = Kp[(size_t)(kt + t) * TDH + dh];
            Vs[t * 64 + dh] = Vp[(size_t)(kt + t) * TDH + dh];
        }
        __syncthreads();

        // S = Q K^T (4x4 per thread), scaled
        float s[4][4];
        #pragma unroll
        for (int i = 0; i < 4; i++)
            #pragma unroll
            for (int j = 0; j < 4; j++) s[i][j] = 0.0f;

        #pragma unroll 8
        for (int kk = 0; kk < 64; kk++) {
            float4 qv = *(const float4*)&Qs[kk * QK_STRIDE + r * 4];
            float4 kv = *(const float4*)&Ks[kk * QK_STRIDE + c * 4];
            float qf[4] = {qv.x, qv.y, qv.z, qv.w};
            float kf[4] = {kv.x, kv.y, kv.z, kv.w};
            #pragma unroll
            for (int ii = 0; ii < 4; ii++)
                #pragma unroll
                for (int jj = 0; jj < 4; jj++)
                    s[ii][jj] += qf[ii] * kf[jj];
        }

        // online softmax update
        #pragma unroll
        for (int ii = 0; ii < 4; ii++) {
            float tm = -1e30f;
            #pragma unroll
            for (int jj = 0; jj < 4; jj++) {
                s[ii][jj] *= 0.125f;
                tm = fmaxf(tm, s[ii][jj]);
            }
            #pragma unroll
            for (int off = 8; off > 0; off >>= 1)
                tm = fmaxf(tm, __shfl_xor_sync(0xffffffffu, tm, off));
            float mn = fmaxf(mrow[ii], tm);
            float al = __expf(mrow[ii] - mn);
            float rs = 0.0f;
            #pragma unroll
            for (int jj = 0; jj < 4; jj++) {
                float p = __expf(s[ii][jj] - mn);
                s[ii][jj] = p;
                rs += p;
            }
            #pragma unroll
            for (int off = 8; off > 0; off >>= 1)
                rs += __shfl_xor_sync(0xffffffffu, rs, off);
            lrow[ii] = lrow[ii] * al + rs;
            mrow[ii] = mn;
            #pragma unroll
            for (int jj = 0; jj < 4; jj++) o[ii][jj] *= al;
        }

        // stage P transposed: Ps[j][i], vectorized STS.128
        #pragma unroll
        for (int jj = 0; jj < 4; jj++) {
            float4 t4 = make_float4(s[0][jj], s[1][jj], s[2][jj], s[3][jj]);
            *(float4*)&Ps[(c * 4 + jj) * QK_STRIDE + r * 4] = t4;
        }
        __syncthreads();

        // O += P V
        #pragma unroll 8
        for (int j = 0; j < 64; j++) {
            float4 pv = *(const float4*)&Ps[j * QK_STRIDE + r * 4];
            float pf[4] = {pv.x, pv.y, pv.z, pv.w};
            float4 vv = *(const float4*)&Vs[j * 64 + c * 4];
            #pragma unroll
            for (int ii = 0; ii < 4; ii++) {
                o[ii][0] += pf[ii] * vv.x;
                o[ii][1] += pf[ii] * vv.y;
                o[ii][2] += pf[ii] * vv.z;
                o[ii][3] += pf[ii] * vv.w;
            }
        }
    }

    // write normalized output into [n][d] row-major scratch
    const int b = bh >> 4;
    const int h = bh & 15;
    #pragma unroll
    for (int ii = 0; ii < 4; ii++) {
        float inv = 1.0f / lrow[ii];
        int t = q0 + r * 4 + ii;
        size_t n = (size_t)b * TT + t;
        float* op = Out + n * TD + h * TDH + c * 4;
        float4 v = make_float4(o[ii][0] * inv, o[ii][1] * inv,
                               o[ii][2] * inv, o[ii][3] * inv);
        *(float4*)op = v;
    }
}

// ---------------------------------------------------------------------------
// Launch
// ---------------------------------------------------------------------------
extern "C" void kernel_launch(void* const* d_in, const int* in_sizes, int n_in,
                              void* d_out, int out_size)
{
    const float* query = (const float*)d_in[0];
    const float* key   = (const float*)d_in[1];
    const float* value = (const float*)d_in[2];
    const float* w_q   = (const float*)d_in[3];
    const float* b_q   = (const float*)d_in[4];
    const float* w_k   = (const float*)d_in[5];
    const float* b_k   = (const float*)d_in[6];
    const float* w_v   = (const float*)d_in[7];
    const float* b_v   = (const float*)d_in[8];
    const float* w_o   = (const float*)d_in[9];
    const float* b_o   = (const float*)d_in[10];
    float* out = (float*)d_out;

    float *qp, *kp, *vp, *ap;
    cudaGetSymbolAddress((void**)&qp, g_q);
    cudaGetSymbolAddress((void**)&kp, g_k);
    cudaGetSymbolAddress((void**)&vp, g_v);
    cudaGetSymbolAddress((void**)&ap, g_attn);

    cudaFuncSetAttribute(gemm_tc, cudaFuncAttributeMaxDynamicSharedMemorySize, GEMM_SMEM);
    cudaFuncSetAttribute(attn_kernel, cudaFuncAttributeMaxDynamicSharedMemorySize,
                         ATTN_SMEM_FLOATS * (int)sizeof(float));

    dim3 gg(TD / 128, NTOK / 128);   // (8, 64)
    gemm_tc<<<gg, 256, GEMM_SMEM>>>(query, w_q, b_q, qp, 0);
    gemm_tc<<<gg, 256, GEMM_SMEM>>>(key,   w_k, b_k, kp, 0);
    gemm_tc<<<gg, 256, GEMM_SMEM>>>(value, w_v, b_v, vp, 0);

    int smem = ATTN_SMEM_FLOATS * (int)sizeof(float);
    attn_kernel<<<dim3(TT / 64, TB * TH), 256, smem>>>(qp, kp, vp, ap);

    gemm_tc<<<gg, 256, GEMM_SMEM>>>(ap, w_o, b_o, out, 1);
}

// round 4
// speedup vs baseline: 2.8814x; 1.9301x over previous
#include <cuda_runtime.h>
#include <cuda_bf16.h>
#include <cstdint>

// Problem constants
#define TB   4
#define TT   2048
#define TD   1024
#define TH   16
#define TDH  64
#define NTOK (TB * TT)          // 8192

// ---------------------------------------------------------------------------
// Scratch (device globals: allocation-free, graph-capture safe)
// ---------------------------------------------------------------------------
__device__ float g_q[TB * TH * TT * TDH];     // [b][h][t][dh]
__device__ float g_k[TB * TH * TT * TDH];
__device__ float g_v[TB * TH * TT * TDH];
__device__ float g_attn[NTOK * TD];           // [n][d] row-major

// ---------------------------------------------------------------------------
// mma.sync helpers (compute_100-safe: sm_80+ features only)
// ---------------------------------------------------------------------------
__device__ __forceinline__ uint32_t smem_u32(const void* p) {
    uint32_t a;
    asm("{ .reg .u64 t; cvta.to.shared.u64 t, %1; cvt.u32.u64 %0, t; }"
        : "=r"(a) : "l"(p));
    return a;
}

#define LDMX4(r, addr) \
    asm volatile("ldmatrix.sync.aligned.m8n8.x4.shared.b16 {%0,%1,%2,%3}, [%4];" \
        : "=r"((r)[0]), "=r"((r)[1]), "=r"((r)[2]), "=r"((r)[3]) : "r"(addr))

#define LDMX4T(r, addr) \
    asm volatile("ldmatrix.sync.aligned.m8n8.x4.trans.shared.b16 {%0,%1,%2,%3}, [%4];" \
        : "=r"((r)[0]), "=r"((r)[1]), "=r"((r)[2]), "=r"((r)[3]) : "r"(addr))

#define MMA16816(d, a, b) \
    asm volatile("mma.sync.aligned.m16n8k16.row.col.f32.bf16.bf16.f32 " \
        "{%0,%1,%2,%3}, {%4,%5,%6,%7}, {%8,%9}, {%0,%1,%2,%3};" \
        : "+f"((d)[0]), "+f"((d)[1]), "+f"((d)[2]), "+f"((d)[3]) \
        : "r"((a)[0]), "r"((a)[1]), "r"((a)[2]), "r"((a)[3]), \
          "r"((b)[0]), "r"((b)[1]))

// split fp32 pair into packed bf16 hi / lo pairs (x -> low half)
__device__ __forceinline__ void split2(float x, float y, uint32_t& hi, uint32_t& lo) {
    __nv_bfloat16 hx = __float2bfloat16(x);
    __nv_bfloat16 hy = __float2bfloat16(y);
    float lx = x - __bfloat162float(hx);
    float ly = y - __bfloat162float(hy);
    __nv_bfloat162 H; H.x = hx; H.y = hy;
    __nv_bfloat162 L; L.x = __float2bfloat16(lx); L.y = __float2bfloat16(ly);
    hi = *reinterpret_cast<uint32_t*>(&H);
    lo = *reinterpret_cast<uint32_t*>(&L);
}

// ---------------------------------------------------------------------------
// Tensor-core GEMM with fused bias (bf16x3 split, fp32-accurate):
//   C[m][n] = sum_k A[m][k] * W[n][k] + bias[n]
// CTA 128x128, BK=32, 256 threads (8 warps: 4M x 2N, warp tile 32x64).
// ---------------------------------------------------------------------------
#define BK 32
#define TSTRIDE 40
#define TILE_U16 (128 * TSTRIDE)
#define TILE_BYTES (TILE_U16 * 2)
#define STAGE_BYTES (4 * TILE_BYTES)
#define GEMM_SMEM (2 * STAGE_BYTES)

__global__ __launch_bounds__(256, 2) void gemm_tc(
    const float* __restrict__ A, const float* __restrict__ W,
    const float* __restrict__ bias, float* __restrict__ Cout, int mode)
{
    extern __shared__ char smem[];
    const uint32_t sbase = smem_u32(smem);
    const int tid  = threadIdx.x;
    const int lane = tid & 31;
    const int wid  = tid >> 5;
    const int warp_m = wid & 3;
    const int warp_n = wid >> 2;
    const int mbase = blockIdx.y * 128;
    const int nbase = blockIdx.x * 128;

    const int lrow = tid >> 3;
    const int lkq  = (tid & 7) * 4;

    const int a_mi   = lane >> 3;
    const int a_roff = ((a_mi & 1) << 3) + (lane & 7);
    const int a_koff = (a_mi >> 1) << 3;
    const int b_roff = (((lane >> 4) & 1) << 3) + (lane & 7);
    const int b_koff = ((lane >> 3) & 1) << 3;

    float4 va[4], vb[4];

    auto LOAD = [&](int cc) {
        const float* ap = A + (size_t)(mbase + lrow) * TD + cc * BK + lkq;
        const float* wp = W + (size_t)(nbase + lrow) * TD + cc * BK + lkq;
        #pragma unroll
        for (int i = 0; i < 4; i++) va[i] = *(const float4*)(ap + (size_t)(32 * i) * TD);
        #pragma unroll
        for (int i = 0; i < 4; i++) vb[i] = *(const float4*)(wp + (size_t)(32 * i) * TD);
    };

    auto STORE = [&](int s) {
        uint16_t* base = (uint16_t*)(smem + s * STAGE_BYTES);
        #pragma unroll
        for (int i = 0; i < 4; i++) {
            int off = (lrow + 32 * i) * TSTRIDE + lkq;
            uint32_t h0, l0, h1, l1;
            split2(va[i].x, va[i].y, h0, l0);
            split2(va[i].z, va[i].w, h1, l1);
            *(uint2*)(base + off)            = make_uint2(h0, h1);
            *(uint2*)(base + TILE_U16 + off) = make_uint2(l0, l1);
            split2(vb[i].x, vb[i].y, h0, l0);
            split2(vb[i].z, vb[i].w, h1, l1);
            *(uint2*)(base + 2 * TILE_U16 + off) = make_uint2(h0, h1);
            *(uint2*)(base + 3 * TILE_U16 + off) = make_uint2(l0, l1);
        }
    };

    float acc[2][8][4];
    #pragma unroll
    for (int mt = 0; mt < 2; mt++)
        #pragma unroll
        for (int nt = 0; nt < 8; nt++)
            #pragma unroll
            for (int r = 0; r < 4; r++) acc[mt][nt][r] = 0.0f;

    LOAD(0);
    STORE(0);
    __syncthreads();

    for (int c = 0; c < TD / BK; c++) {
        if (c < TD / BK - 1) LOAD(c + 1);

        const uint32_t sa = sbase + (c & 1) * STAGE_BYTES;
        const uint32_t sb = sa + 2 * TILE_BYTES;

        #pragma unroll
        for (int ks = 0; ks < 2; ks++) {
            const int k0 = ks * 16;
            uint32_t a_hi[2][4], a_lo[2][4];
            #pragma unroll
            for (int mt = 0; mt < 2; mt++) {
                int row = warp_m * 32 + mt * 16 + a_roff;
                uint32_t ad = sa + (uint32_t)(row * TSTRIDE + k0 + a_koff) * 2;
                LDMX4(a_hi[mt], ad);
                LDMX4(a_lo[mt], ad + TILE_BYTES);
            }
            #pragma unroll
            for (int ntp = 0; ntp < 4; ntp++) {
                int row = warp_n * 64 + ntp * 16 + b_roff;
                uint32_t bd = sb + (uint32_t)(row * TSTRIDE + k0 + b_koff) * 2;
                uint32_t bh[4], bl[4];
                LDMX4(bh, bd);
                LDMX4(bl, bd + TILE_BYTES);
                #pragma unroll
                for (int mt = 0; mt < 2; mt++) {
                    MMA16816(acc[mt][ntp * 2],     a_hi[mt], &bh[0]);
                    MMA16816(acc[mt][ntp * 2],     a_hi[mt], &bl[0]);
                    MMA16816(acc[mt][ntp * 2],     a_lo[mt], &bh[0]);
                    MMA16816(acc[mt][ntp * 2 + 1], a_hi[mt], &bh[2]);
                    MMA16816(acc[mt][ntp * 2 + 1], a_hi[mt], &bl[2]);
                    MMA16816(acc[mt][ntp * 2 + 1], a_lo[mt], &bh[2]);
                }
            }
        }
        __syncthreads();
        if (c < TD / BK - 1) {
            STORE((c + 1) & 1);
            __syncthreads();
        }
    }

    const int gid = lane >> 2;
    const int tig = lane & 3;
    float2 bb[8];
    #pragma unroll
    for (int nt = 0; nt < 8; nt++)
        bb[nt] = *(const float2*)&bias[nbase + warp_n * 64 + nt * 8 + tig * 2];

    #pragma unroll
    for (int mt = 0; mt < 2; mt++) {
        #pragma unroll
        for (int half = 0; half < 2; half++) {
            int m = mbase + warp_m * 32 + mt * 16 + gid + half * 8;
            if (mode == 0) {
                int b = m >> 11;
                int t = m & (TT - 1);
                int h = (nbase + warp_n * 64) >> 6;
                float* op = Cout + (((size_t)(b * TH + h)) * TT + t) * TDH;
                #pragma unroll
                for (int nt = 0; nt < 8; nt++) {
                    float2 v;
                    v.x = acc[mt][nt][half * 2 + 0] + bb[nt].x;
                    v.y = acc[mt][nt][half * 2 + 1] + bb[nt].y;
                    *(float2*)(op + nt * 8 + tig * 2) = v;
                }
            } else {
                float* op = Cout + (size_t)m * TD + nbase + warp_n * 64;
                #pragma unroll
                for (int nt = 0; nt < 8; nt++) {
                    float2 v;
                    v.x = acc[mt][nt][half * 2 + 0] + bb[nt].x;
                    v.y = acc[mt][nt][half * 2 + 1] + bb[nt].y;
                    *(float2*)(op + nt * 8 + tig * 2) = v;
                }
            }
        }
    }
}

// ---------------------------------------------------------------------------
// Tensor-core flash attention (bf16x3 split).
// Block = 128 queries x one (b,h); 8 warps, warp = 16 query rows.
// KV tile 64. S/P kept in register fragments; P fed to PV mma directly.
// smem: Qh/Ql [128][72], Kh/Kl [64][72], Vh/Vl [64][72] (bf16, stride 72).
// ---------------------------------------------------------------------------
#define SQ 72
#define OFF_QH 0
#define OFF_QL (128 * SQ)            // 9216
#define OFF_KH (2 * 128 * SQ)        // 18432
#define OFF_KL (OFF_KH + 64 * SQ)
#define OFF_VH (OFF_KH + 2 * 64 * SQ)
#define OFF_VL (OFF_VH + 64 * SQ)
#define ATTN_SMEM ((2 * 128 + 4 * 64) * SQ * 2)   // 73728 bytes

__global__ __launch_bounds__(256, 2) void attn_tc(
    const float* __restrict__ Q, const float* __restrict__ Kg_,
    const float* __restrict__ Vg_, float* __restrict__ Out)
{
    extern __shared__ uint16_t us[];
    const uint32_t sbase = smem_u32(us);
    const int tid  = threadIdx.x;
    const int lane = tid & 31;
    const int wid  = tid >> 5;        // warp owns rows wid*16..+15
    const int bh = blockIdx.y;
    const int q0 = blockIdx.x * 128;

    const float* Qp = Q   + (size_t)bh * TT * TDH;
    const float* Kp = Kg_ + (size_t)bh * TT * TDH;
    const float* Vp = Vg_ + (size_t)bh * TT * TDH;

    // fragment address components
    const int a_mi   = lane >> 3;
    const int a_roff = ((a_mi & 1) << 3) + (lane & 7);
    const int a_koff = (a_mi >> 1) << 3;
    const int b_roff = (((lane >> 4) & 1) << 3) + (lane & 7);
    const int b_koff = ((lane >> 3) & 1) << 3;
    const int v_toff = (((lane >> 3) & 1) << 3) + (lane & 7);
    const int v_dhoff = (lane >> 4) << 3;
    const int gid = lane >> 2;
    const int tig = lane & 3;

    // load Q tile: pre-scale by 0.125 (exact), split hi/lo
    for (int i = tid; i < 128 * 16; i += 256) {
        int row = i >> 4, c4 = (i & 15) * 4;
        float4 v = *(const float4*)(Qp + (size_t)(q0 + row) * TDH + c4);
        v.x *= 0.125f; v.y *= 0.125f; v.z *= 0.125f; v.w *= 0.125f;
        uint32_t h0, l0, h1, l1;
        split2(v.x, v.y, h0, l0);
        split2(v.z, v.w, h1, l1);
        *(uint2*)(us + OFF_QH + row * SQ + c4) = make_uint2(h0, h1);
        *(uint2*)(us + OFF_QL + row * SQ + c4) = make_uint2(l0, l1);
    }

    float oacc[8][4];
    #pragma unroll
    for (int nt = 0; nt < 8; nt++)
        #pragma unroll
        for (int r = 0; r < 4; r++) oacc[nt][r] = 0.0f;
    float mrow0 = -1e30f, mrow1 = -1e30f, lrow0 = 0.0f, lrow1 = 0.0f;

    for (int kt = 0; kt < TT; kt += 64) {
        __syncthreads();
        // load K,V tiles, split hi/lo
        for (int i = tid; i < 64 * 16; i += 256) {
            int row = i >> 4, c4 = (i & 15) * 4;
            float4 kv = *(const float4*)(Kp + (size_t)(kt + row) * TDH + c4);
            uint32_t h0, l0, h1, l1;
            split2(kv.x, kv.y, h0, l0);
            split2(kv.z, kv.w, h1, l1);
            *(uint2*)(us + OFF_KH + row * SQ + c4) = make_uint2(h0, h1);
            *(uint2*)(us + OFF_KL + row * SQ + c4) = make_uint2(l0, l1);
            float4 vv = *(const float4*)(Vp + (size_t)(kt + row) * TDH + c4);
            split2(vv.x, vv.y, h0, l0);
            split2(vv.z, vv.w, h1, l1);
            *(uint2*)(us + OFF_VH + row * SQ + c4) = make_uint2(h0, h1);
            *(uint2*)(us + OFF_VL + row * SQ + c4) = make_uint2(l0, l1);
        }
        __syncthreads();

        // ---- S = Q K^T (scaled; Q pre-scaled) ----
        float sacc[8][4];
        #pragma unroll
        for (int nt = 0; nt < 8; nt++)
            #pragma unroll
            for (int r = 0; r < 4; r++) sacc[nt][r] = 0.0f;

        #pragma unroll
        for (int ks = 0; ks < 4; ks++) {
            const int k0 = ks * 16;
            uint32_t ah[4], alr[4];
            {
                uint32_t ad = sbase + (uint32_t)((wid * 16 + a_roff) * SQ + k0 + a_koff) * 2;
                LDMX4(ah,  ad + OFF_QH * 2);
                LDMX4(alr, ad + OFF_QL * 2);
            }
            #pragma unroll
            for (int np = 0; np < 4; np++) {
                uint32_t bd = sbase + (uint32_t)((np * 16 + b_roff) * SQ + k0 + b_koff) * 2;
                uint32_t bh[4], bl[4];
                LDMX4(bh, bd + OFF_KH * 2);
                LDMX4(bl, bd + OFF_KL * 2);
                MMA16816(sacc[np * 2],     ah,  &bh[0]);
                MMA16816(sacc[np * 2],     ah,  &bl[0]);
                MMA16816(sacc[np * 2],     alr, &bh[0]);
                MMA16816(sacc[np * 2 + 1], ah,  &bh[2]);
                MMA16816(sacc[np * 2 + 1], ah,  &bl[2]);
                MMA16816(sacc[np * 2 + 1], alr, &bh[2]);
            }
        }

        // ---- online softmax on fragments (rows gid, gid+8) ----
        float mx0 = -1e30f, mx1 = -1e30f;
        #pragma unroll
        for (int nt = 0; nt < 8; nt++) {
            mx0 = fmaxf(mx0, fmaxf(sacc[nt][0], sacc[nt][1]));
            mx1 = fmaxf(mx1, fmaxf(sacc[nt][2], sacc[nt][3]));
        }
        mx0 = fmaxf(mx0, __shfl_xor_sync(0xffffffffu, mx0, 1));
        mx0 = fmaxf(mx0, __shfl_xor_sync(0xffffffffu, mx0, 2));
        mx1 = fmaxf(mx1, __shfl_xor_sync(0xffffffffu, mx1, 1));
        mx1 = fmaxf(mx1, __shfl_xor_sync(0xffffffffu, mx1, 2));
        float mn0 = fmaxf(mrow0, mx0);
        float mn1 = fmaxf(mrow1, mx1);
        float al0 = __expf(mrow0 - mn0);
        float al1 = __expf(mrow1 - mn1);
        float rs0 = 0.0f, rs1 = 0.0f;
        #pragma unroll
        for (int nt = 0; nt < 8; nt++) {
            sacc[nt][0] = __expf(sacc[nt][0] - mn0);
            sacc[nt][1] = __expf(sacc[nt][1] - mn0);
            sacc[nt][2] = __expf(sacc[nt][2] - mn1);
            sacc[nt][3] = __expf(sacc[nt][3] - mn1);
            rs0 += sacc[nt][0] + sacc[nt][1];
            rs1 += sacc[nt][2] + sacc[nt][3];
        }
        rs0 += __shfl_xor_sync(0xffffffffu, rs0, 1);
        rs0 += __shfl_xor_sync(0xffffffffu, rs0, 2);
        rs1 += __shfl_xor_sync(0xffffffffu, rs1, 1);
        rs1 += __shfl_xor_sync(0xffffffffu, rs1, 2);
        lrow0 = lrow0 * al0 + rs0;
        lrow1 = lrow1 * al1 + rs1;
        mrow0 = mn0; mrow1 = mn1;
        #pragma unroll
        for (int nt = 0; nt < 8; nt++) {
            oacc[nt][0] *= al0; oacc[nt][1] *= al0;
            oacc[nt][2] *= al1; oacc[nt][3] *= al1;
        }

        // ---- O += P V  (P fragments from sacc; V via ldmatrix.trans) ----
        #pragma unroll
        for (int kc = 0; kc < 4; kc++) {
            uint32_t pah[4], pal[4];
            split2(sacc[2 * kc][0],     sacc[2 * kc][1],     pah[0], pal[0]);
            split2(sacc[2 * kc][2],     sacc[2 * kc][3],     pah[1], pal[1]);
            split2(sacc[2 * kc + 1][0], sacc[2 * kc + 1][1], pah[2], pal[2]);
            split2(sacc[2 * kc + 1][2], sacc[2 * kc + 1][3], pah[3], pal[3]);
            #pragma unroll
            for (int np = 0; np < 4; np++) {
                uint32_t vd = sbase +
                    (uint32_t)((kc * 16 + v_toff) * SQ + np * 16 + v_dhoff) * 2;
                uint32_t bh[4], bl[4];
                LDMX4T(bh, vd + OFF_VH * 2);
                LDMX4T(bl, vd + OFF_VL * 2);
                MMA16816(oacc[np * 2],     pah, &bh[0]);
                MMA16816(oacc[np * 2],     pah, &bl[0]);
                MMA16816(oacc[np * 2],     pal, &bh[0]);
                MMA16816(oacc[np * 2 + 1], pah, &bh[2]);
                MMA16816(oacc[np * 2 + 1], pah, &bl[2]);
                MMA16816(oacc[np * 2 + 1], pal, &bh[2]);
            }
        }
    }

    // ---- epilogue: normalize and write to [n][d] scratch ----
    const int b = bh >> 4;
    const int h = bh & 15;
    const float inv0 = 1.0f / lrow0;
    const float inv1 = 1.0f / lrow1;
    #pragma unroll
    for (int half = 0; half < 2; half++) {
        int t = q0 + wid * 16 + gid + half * 8;
        float inv = half ? inv1 : inv0;
        size_t n = (size_t)b * TT + t;
        float* op = Out + n * TD + h * TDH;
        #pragma unroll
        for (int nt = 0; nt < 8; nt++) {
            float2 v;
            v.x = oacc[nt][half * 2 + 0] * inv;
            v.y = oacc[nt][half * 2 + 1] * inv;
            *(float2*)(op + nt * 8 + tig * 2) = v;
        }
    }
}

// ---------------------------------------------------------------------------
// Launch
// ---------------------------------------------------------------------------
extern "C" void kernel_launch(void* const* d_in, const int* in_sizes, int n_in,
                              void* d_out, int out_size)
{
    const float* query = (const float*)d_in[0];
    const float* key   = (const float*)d_in[1];
    const float* value = (const float*)d_in[2];
    const float* w_q   = (const float*)d_in[3];
    const float* b_q   = (const float*)d_in[4];
    const float* w_k   = (const float*)d_in[5];
    const float* b_k   = (const float*)d_in[6];
    const float* w_v   = (const float*)d_in[7];
    const float* b_v   = (const float*)d_in[8];
    const float* w_o   = (const float*)d_in[9];
    const float* b_o   = (const float*)d_in[10];
    float* out = (float*)d_out;

    float *qp, *kp, *vp, *ap;
    cudaGetSymbolAddress((void**)&qp, g_q);
    cudaGetSymbolAddress((void**)&kp, g_k);
    cudaGetSymbolAddress((void**)&vp, g_v);
    cudaGetSymbolAddress((void**)&ap, g_attn);

    cudaFuncSetAttribute(gemm_tc, cudaFuncAttributeMaxDynamicSharedMemorySize, GEMM_SMEM);
    cudaFuncSetAttribute(attn_tc, cudaFuncAttributeMaxDynamicSharedMemorySize, ATTN_SMEM);

    dim3 gg(TD / 128, NTOK / 128);   // (8, 64)
    gemm_tc<<<gg, 256, GEMM_SMEM>>>(query, w_q, b_q, qp, 0);
    gemm_tc<<<gg, 256, GEMM_SMEM>>>(key,   w_k, b_k, kp, 0);
    gemm_tc<<<gg, 256, GEMM_SMEM>>>(value, w_v, b_v, vp, 0);

    attn_tc<<<dim3(TT / 128, TB * TH), 256, ATTN_SMEM>>>(qp, kp, vp, ap);

    gemm_tc<<<gg, 256, GEMM_SMEM>>>(ap, w_o, b_o, out, 1);
}

// round 5
// speedup vs baseline: 3.2697x; 1.1348x over previous
#include <cuda_runtime.h>
#include <cuda_bf16.h>
#include <cstdint>

// Problem constants
#define TB   4
#define TT   2048
#define TD   1024
#define TH   16
#define TDH  64
#define NTOK (TB * TT)          // 8192

#define QSCALE (0.125f * 1.44269504088896f)   // 1/sqrt(64) * log2(e)

// ---------------------------------------------------------------------------
// Scratch (device globals: allocation-free, graph-capture safe)  bf16 hi/lo
// ---------------------------------------------------------------------------
__device__ uint16_t g_ah[NTOK * TD], g_al[NTOK * TD];          // A conversions (reused)
__device__ uint16_t g_wh[4 * TD * TD], g_wl[4 * TD * TD];      // W conversions
__device__ uint16_t g_qh[TB * TH * TT * TDH], g_ql[TB * TH * TT * TDH];
__device__ uint16_t g_kh[TB * TH * TT * TDH], g_kl[TB * TH * TT * TDH];
__device__ uint16_t g_vh[TB * TH * TT * TDH], g_vl[TB * TH * TT * TDH];
__device__ uint16_t g_oh[NTOK * TD], g_ol[NTOK * TD];          // attn out

// ---------------------------------------------------------------------------
// helpers (compute_100-safe: sm_80+ features only)
// ---------------------------------------------------------------------------
__device__ __forceinline__ uint32_t smem_u32(const void* p) {
    uint32_t a;
    asm("{ .reg .u64 t; cvta.to.shared.u64 t, %1; cvt.u32.u64 %0, t; }"
        : "=r"(a) : "l"(p));
    return a;
}

#define LDMX4(r, addr) \
    asm volatile("ldmatrix.sync.aligned.m8n8.x4.shared.b16 {%0,%1,%2,%3}, [%4];" \
        : "=r"((r)[0]), "=r"((r)[1]), "=r"((r)[2]), "=r"((r)[3]) : "r"(addr))

#define LDMX4T(r, addr) \
    asm volatile("ldmatrix.sync.aligned.m8n8.x4.trans.shared.b16 {%0,%1,%2,%3}, [%4];" \
        : "=r"((r)[0]), "=r"((r)[1]), "=r"((r)[2]), "=r"((r)[3]) : "r"(addr))

#define MMA16816(d, a, b) \
    asm volatile("mma.sync.aligned.m16n8k16.row.col.f32.bf16.bf16.f32 " \
        "{%0,%1,%2,%3}, {%4,%5,%6,%7}, {%8,%9}, {%0,%1,%2,%3};" \
        : "+f"((d)[0]), "+f"((d)[1]), "+f"((d)[2]), "+f"((d)[3]) \
        : "r"((a)[0]), "r"((a)[1]), "r"((a)[2]), "r"((a)[3]), \
          "r"((b)[0]), "r"((b)[1]))

#define CP16(dst, src) \
    asm volatile("cp.async.cg.shared.global [%0], [%1], 16;" \
        :: "r"((uint32_t)(dst)), "l"(src))
#define CP_COMMIT() asm volatile("cp.async.commit_group;" ::: "memory")
#define CP_WAIT0()  asm volatile("cp.async.wait_group 0;" ::: "memory")

__device__ __forceinline__ float ex2(float x) {
    float y;
    asm("ex2.approx.f32 %0, %1;" : "=f"(y) : "f"(x));
    return y;
}

// split fp32 pair into packed bf16 hi / lo pairs (x -> low half)
__device__ __forceinline__ void split2(float x, float y, uint32_t& hi, uint32_t& lo) {
    __nv_bfloat16 hx = __float2bfloat16(x);
    __nv_bfloat16 hy = __float2bfloat16(y);
    float lx = x - __bfloat162float(hx);
    float ly = y - __bfloat162float(hy);
    __nv_bfloat162 H; H.x = hx; H.y = hy;
    __nv_bfloat162 L; L.x = __float2bfloat16(lx); L.y = __float2bfloat16(ly);
    hi = *reinterpret_cast<uint32_t*>(&H);
    lo = *reinterpret_cast<uint32_t*>(&L);
}

// ---------------------------------------------------------------------------
// conversion kernel: fp32 -> bf16 hi/lo
// ---------------------------------------------------------------------------
__global__ void conv_split(const float4* __restrict__ in,
                           uint2* __restrict__ hi, uint2* __restrict__ lo, int n4)
{
    int i = blockIdx.x * blockDim.x + threadIdx.x;
    if (i < n4) {
        float4 v = in[i];
        uint32_t h0, l0, h1, l1;
        split2(v.x, v.y, h0, l0);
        split2(v.z, v.w, h1, l1);
        hi[i] = make_uint2(h0, h1);
        lo[i] = make_uint2(l0, l1);
    }
}

// ---------------------------------------------------------------------------
// Tensor-core GEMM, all operands pre-split bf16 hi/lo in gmem:
//   C[m][n] = sum_k A[m][k] * W[n][k] + bias[n], then *scale
// CTA 128x128, BK=32, 256 threads (8 warps: 4M x 2N), cp.async double buffer.
// mode 0: write bf16 hi/lo scattered to [b][h][t][dh]; mode 1: fp32 [m][n].
// ---------------------------------------------------------------------------
#define BK 32
#define TSTRIDE 40
#define TILE_U16 (128 * TSTRIDE)
#define TILE_BYTES (TILE_U16 * 2)          // 10240
#define STAGE_BYTES (4 * TILE_BYTES)       // 40960
#define GEMM_SMEM (2 * STAGE_BYTES)        // 81920
#define NCHUNK (TD / BK)                   // 32

__global__ __launch_bounds__(256, 2) void gemm_bf16(
    const uint16_t* __restrict__ Ah, const uint16_t* __restrict__ Al,
    const uint16_t* __restrict__ Wh, const uint16_t* __restrict__ Wl,
    const float* __restrict__ bias, float scale,
    uint16_t* __restrict__ Oh, uint16_t* __restrict__ Ol,
    float* __restrict__ Of, int mode)
{
    extern __shared__ char smem[];
    const uint32_t sbase = smem_u32(smem);
    const int tid  = threadIdx.x;
    const int lane = tid & 31;
    const int wid  = tid >> 5;
    const int warp_m = wid & 3;
    const int warp_n = wid >> 2;
    const int mbase = blockIdx.y * 128;
    const int nbase = blockIdx.x * 128;

    const int a_mi   = lane >> 3;
    const int a_roff = ((a_mi & 1) << 3) + (lane & 7);
    const int a_koff = (a_mi >> 1) << 3;
    const int b_roff = (((lane >> 4) & 1) << 3) + (lane & 7);
    const int b_koff = ((lane >> 3) & 1) << 3;

    auto ISSUE = [&](int c) {
        uint32_t dst = sbase + (c & 1) * STAGE_BYTES;
        #pragma unroll
        for (int half = 0; half < 2; half++) {
            int id = tid + half * 256;
            int row = id >> 2, cq = id & 3;
            uint32_t so = dst + (uint32_t)(row * TSTRIDE + cq * 8) * 2;
            size_t goA = (size_t)(mbase + row) * TD + c * BK + cq * 8;
            size_t goW = (size_t)(nbase + row) * TD + c * BK + cq * 8;
            CP16(so,                  Ah + goA);
            CP16(so + TILE_BYTES,     Al + goA);
            CP16(so + 2 * TILE_BYTES, Wh + goW);
            CP16(so + 3 * TILE_BYTES, Wl + goW);
        }
    };

    float acc[2][8][4];
    #pragma unroll
    for (int mt = 0; mt < 2; mt++)
        #pragma unroll
        for (int nt = 0; nt < 8; nt++)
            #pragma unroll
            for (int r = 0; r < 4; r++) acc[mt][nt][r] = 0.0f;

    ISSUE(0);
    CP_COMMIT();

    for (int c = 0; c < NCHUNK; c++) {
        CP_WAIT0();
        __syncthreads();
        if (c < NCHUNK - 1) { ISSUE(c + 1); CP_COMMIT(); }

        const uint32_t sa = sbase + (c & 1) * STAGE_BYTES;
        const uint32_t sb = sa + 2 * TILE_BYTES;

        #pragma unroll
        for (int ks = 0; ks < 2; ks++) {
            const int k0 = ks * 16;
            uint32_t a_hi[2][4], a_lo[2][4];
            #pragma unroll
            for (int mt = 0; mt < 2; mt++) {
                int row = warp_m * 32 + mt * 16 + a_roff;
                uint32_t ad = sa + (uint32_t)(row * TSTRIDE + k0 + a_koff) * 2;
                LDMX4(a_hi[mt], ad);
                LDMX4(a_lo[mt], ad + TILE_BYTES);
            }
            #pragma unroll
            for (int ntp = 0; ntp < 4; ntp++) {
                int row = warp_n * 64 + ntp * 16 + b_roff;
                uint32_t bd = sb + (uint32_t)(row * TSTRIDE + k0 + b_koff) * 2;
                uint32_t bh[4], bl[4];
                LDMX4(bh, bd);
                LDMX4(bl, bd + TILE_BYTES);
                #pragma unroll
                for (int mt = 0; mt < 2; mt++) {
                    MMA16816(acc[mt][ntp * 2],     a_hi[mt], &bh[0]);
                    MMA16816(acc[mt][ntp * 2],     a_hi[mt], &bl[0]);
                    MMA16816(acc[mt][ntp * 2],     a_lo[mt], &bh[0]);
                    MMA16816(acc[mt][ntp * 2 + 1], a_hi[mt], &bh[2]);
                    MMA16816(acc[mt][ntp * 2 + 1], a_hi[mt], &bl[2]);
                    MMA16816(acc[mt][ntp * 2 + 1], a_lo[mt], &bh[2]);
                }
            }
        }
        __syncthreads();
    }

    // epilogue
    const int gid = lane >> 2;
    const int tig = lane & 3;
    float2 bb[8];
    #pragma unroll
    for (int nt = 0; nt < 8; nt++)
        bb[nt] = *(const float2*)&bias[nbase + warp_n * 64 + nt * 8 + tig * 2];

    #pragma unroll
    for (int mt = 0; mt < 2; mt++) {
        #pragma unroll
        for (int half = 0; half < 2; half++) {
            int m = mbase + warp_m * 32 + mt * 16 + gid + half * 8;
            if (mode == 0) {
                int b = m >> 11;
                int t = m & (TT - 1);
                int h = (nbase + warp_n * 64) >> 6;
                size_t base = (((size_t)(b * TH + h)) * TT + t) * TDH;
                #pragma unroll
                for (int nt = 0; nt < 8; nt++) {
                    float vx = (acc[mt][nt][half * 2 + 0] + bb[nt].x) * scale;
                    float vy = (acc[mt][nt][half * 2 + 1] + bb[nt].y) * scale;
                    uint32_t hh, ll;
                    split2(vx, vy, hh, ll);
                    *(uint32_t*)(Oh + base + nt * 8 + tig * 2) = hh;
                    *(uint32_t*)(Ol + base + nt * 8 + tig * 2) = ll;
                }
            } else {
                float* op = Of + (size_t)m * TD + nbase + warp_n * 64;
                #pragma unroll
                for (int nt = 0; nt < 8; nt++) {
                    float2 v;
                    v.x = acc[mt][nt][half * 2 + 0] + bb[nt].x;
                    v.y = acc[mt][nt][half * 2 + 1] + bb[nt].y;
                    *(float2*)(op + nt * 8 + tig * 2) = v;
                }
            }
        }
    }
}

// ---------------------------------------------------------------------------
// Tensor-core flash attention (bf16x3), all inputs pre-split bf16 hi/lo.
// Block = 128 queries x one (b,h); 8 warps, warp = 16 query rows; KV tile 64.
// cp.async double-buffered KV. Softmax in base-2 (Q pre-scaled by log2e/8).
// smem (u16): QH[128][72], QL[128][72], 2 stages of {KH,KL,VH,VL}[64][72].
// ---------------------------------------------------------------------------
#define SQ 72
#define OFF_QH 0
#define OFF_QL (128 * SQ)                 // 9216
#define KVBASE (2 * 128 * SQ)             // 18432
#define KVARR  (64 * SQ)                  // 4608
#define KVSTAGE (4 * KVARR)               // 18432
#define ATTN_SMEM ((KVBASE + 2 * KVSTAGE) * 2)   // 110592 bytes

__global__ __launch_bounds__(256, 2) void attn_tc(
    const uint16_t* __restrict__ Qh, const uint16_t* __restrict__ Ql,
    const uint16_t* __restrict__ Kh, const uint16_t* __restrict__ Kl,
    const uint16_t* __restrict__ Vh, const uint16_t* __restrict__ Vl,
    uint16_t* __restrict__ Oh, uint16_t* __restrict__ Ol)
{
    extern __shared__ uint16_t us[];
    const uint32_t sbase = smem_u32(us);
    const int tid  = threadIdx.x;
    const int lane = tid & 31;
    const int wid  = tid >> 5;
    const int bh = blockIdx.y;
    const int q0 = blockIdx.x * 128;

    const size_t bho = (size_t)bh * TT * TDH;
    const uint16_t* kp[4] = {Kh + bho, Kl + bho, Vh + bho, Vl + bho};

    const int a_mi   = lane >> 3;
    const int a_roff = ((a_mi & 1) << 3) + (lane & 7);
    const int a_koff = (a_mi >> 1) << 3;
    const int b_roff = (((lane >> 4) & 1) << 3) + (lane & 7);
    const int b_koff = ((lane >> 3) & 1) << 3;
    const int v_toff = (((lane >> 3) & 1) << 3) + (lane & 7);
    const int v_dhoff = (lane >> 4) << 3;
    const int gid = lane >> 2;
    const int tig = lane & 3;

    // Q tile loads (group 0)
    #pragma unroll
    for (int i = 0; i < 8; i++) {
        const uint16_t* src = (i < 4 ? Qh : Ql) + bho;
        int rid = ((i & 3) << 5) + (tid >> 3);
        int cq  = tid & 7;
        uint32_t dst = sbase +
            (uint32_t)(((i < 4) ? OFF_QH : OFF_QL) + rid * SQ + cq * 8) * 2;
        CP16(dst, src + (size_t)(q0 + rid) * TDH + cq * 8);
    }

    auto ISSUE_KV = [&](int kt, int s) {
        uint32_t stb = sbase + (uint32_t)(KVBASE + s * KVSTAGE) * 2;
        #pragma unroll
        for (int i = 0; i < 8; i++) {
            const int arr = i >> 1;
            int rid = ((i & 1) << 5) + (tid >> 3);
            int cq  = tid & 7;
            uint32_t dst = stb + (uint32_t)(arr * KVARR + rid * SQ + cq * 8) * 2;
            CP16(dst, kp[arr] + (size_t)(kt + rid) * TDH + cq * 8);
        }
    };

    ISSUE_KV(0, 0);
    CP_COMMIT();

    float oacc[8][4];
    #pragma unroll
    for (int nt = 0; nt < 8; nt++)
        #pragma unroll
        for (int r = 0; r < 4; r++) oacc[nt][r] = 0.0f;
    float mrow0 = -1e30f, mrow1 = -1e30f, lrow0 = 0.0f, lrow1 = 0.0f;

    const int NKV = TT / 64;
    for (int ti = 0; ti < NKV; ti++) {
        CP_WAIT0();
        __syncthreads();
        if (ti < NKV - 1) { ISSUE_KV((ti + 1) * 64, (ti + 1) & 1); CP_COMMIT(); }

        const uint32_t kb = (uint32_t)(KVBASE + (ti & 1) * KVSTAGE);

        // ---- S = Q K^T (Q pre-scaled by log2e/8) ----
        float sacc[8][4];
        #pragma unroll
        for (int nt = 0; nt < 8; nt++)
            #pragma unroll
            for (int r = 0; r < 4; r++) sacc[nt][r] = 0.0f;

        #pragma unroll
        for (int ks = 0; ks < 4; ks++) {
            const int k0 = ks * 16;
            uint32_t ah[4], alr[4];
            {
                uint32_t ad = sbase + (uint32_t)((wid * 16 + a_roff) * SQ + k0 + a_koff) * 2;
                LDMX4(ah,  ad + OFF_QH * 2);
                LDMX4(alr, ad + OFF_QL * 2);
            }
            #pragma unroll
            for (int np = 0; np < 4; np++) {
                uint32_t bd = sbase +
                    (uint32_t)(kb + (np * 16 + b_roff) * SQ + k0 + b_koff) * 2;
                uint32_t bh[4], bl[4];
                LDMX4(bh, bd);
                LDMX4(bl, bd + KVARR * 2);
                MMA16816(sacc[np * 2],     ah,  &bh[0]);
                MMA16816(sacc[np * 2],     ah,  &bl[0]);
                MMA16816(sacc[np * 2],     alr, &bh[0]);
                MMA16816(sacc[np * 2 + 1], ah,  &bh[2]);
                MMA16816(sacc[np * 2 + 1], ah,  &bl[2]);
                MMA16816(sacc[np * 2 + 1], alr, &bh[2]);
            }
        }

        // ---- online softmax (base-2) on fragments (rows gid, gid+8) ----
        float mx0 = -1e30f, mx1 = -1e30f;
        #pragma unroll
        for (int nt = 0; nt < 8; nt++) {
            mx0 = fmaxf(mx0, fmaxf(sacc[nt][0], sacc[nt][1]));
            mx1 = fmaxf(mx1, fmaxf(sacc[nt][2], sacc[nt][3]));
        }
        mx0 = fmaxf(mx0, __shfl_xor_sync(0xffffffffu, mx0, 1));
        mx0 = fmaxf(mx0, __shfl_xor_sync(0xffffffffu, mx0, 2));
        mx1 = fmaxf(mx1, __shfl_xor_sync(0xffffffffu, mx1, 1));
        mx1 = fmaxf(mx1, __shfl_xor_sync(0xffffffffu, mx1, 2));
        float mn0 = fmaxf(mrow0, mx0);
        float mn1 = fmaxf(mrow1, mx1);
        float al0 = ex2(mrow0 - mn0);
        float al1 = ex2(mrow1 - mn1);
        float rs0 = 0.0f, rs1 = 0.0f;
        #pragma unroll
        for (int nt = 0; nt < 8; nt++) {
            sacc[nt][0] = ex2(sacc[nt][0] - mn0);
            sacc[nt][1] = ex2(sacc[nt][1] - mn0);
            sacc[nt][2] = ex2(sacc[nt][2] - mn1);
            sacc[nt][3] = ex2(sacc[nt][3] - mn1);
            rs0 += sacc[nt][0] + sacc[nt][1];
            rs1 += sacc[nt][2] + sacc[nt][3];
        }
        rs0 += __shfl_xor_sync(0xffffffffu, rs0, 1);
        rs0 += __shfl_xor_sync(0xffffffffu, rs0, 2);
        rs1 += __shfl_xor_sync(0xffffffffu, rs1, 1);
        rs1 += __shfl_xor_sync(0xffffffffu, rs1, 2);
        lrow0 = lrow0 * al0 + rs0;
        lrow1 = lrow1 * al1 + rs1;
        mrow0 = mn0; mrow1 = mn1;
        #pragma unroll
        for (int nt = 0; nt < 8; nt++) {
            oacc[nt][0] *= al0; oacc[nt][1] *= al0;
            oacc[nt][2] *= al1; oacc[nt][3] *= al1;
        }

        // ---- O += P V  (P hi/lo fragments from sacc; V via ldmatrix.trans) ----
        #pragma unroll
        for (int kc = 0; kc < 4; kc++) {
            uint32_t pah[4], pal[4];
            split2(sacc[2 * kc][0],     sacc[2 * kc][1],     pah[0], pal[0]);
            split2(sacc[2 * kc][2],     sacc[2 * kc][3],     pah[1], pal[1]);
            split2(sacc[2 * kc + 1][0], sacc[2 * kc + 1][1], pah[2], pal[2]);
            split2(sacc[2 * kc + 1][2], sacc[2 * kc + 1][3], pah[3], pal[3]);
            #pragma unroll
            for (int np = 0; np < 4; np++) {
                uint32_t vd = sbase +
                    (uint32_t)(kb + 2 * KVARR + (kc * 16 + v_toff) * SQ + np * 16 + v_dhoff) * 2;
                uint32_t bh[4], bl[4];
                LDMX4T(bh, vd);
                LDMX4T(bl, vd + KVARR * 2);
                MMA16816(oacc[np * 2],     pah, &bh[0]);
                MMA16816(oacc[np * 2],     pah, &bl[0]);
                MMA16816(oacc[np * 2],     pal, &bh[0]);
                MMA16816(oacc[np * 2 + 1], pah, &bh[2]);
                MMA16816(oacc[np * 2 + 1], pah, &bl[2]);
                MMA16816(oacc[np * 2 + 1], pal, &bh[2]);
            }
        }
    }

    // ---- epilogue: normalize, split, write bf16 hi/lo to [n][d] ----
    const int b = bh >> 4;
    const int h = bh & 15;
    const float inv0 = 1.0f / lrow0;
    const float inv1 = 1.0f / lrow1;
    #pragma unroll
    for (int half = 0; half < 2; half++) {
        int t = q0 + wid * 16 + gid + half * 8;
        float inv = half ? inv1 : inv0;
        size_t n = (size_t)b * TT + t;
        size_t base = n * TD + h * TDH;
        #pragma unroll
        for (int nt = 0; nt < 8; nt++) {
            float vx = oacc[nt][half * 2 + 0] * inv;
            float vy = oacc[nt][half * 2 + 1] * inv;
            uint32_t hh, ll;
            split2(vx, vy, hh, ll);
            *(uint32_t*)(Oh + base + nt * 8 + tig * 2) = hh;
            *(uint32_t*)(Ol + base + nt * 8 + tig * 2) = ll;
        }
    }
}

// ---------------------------------------------------------------------------
// Launch
// ---------------------------------------------------------------------------
extern "C" void kernel_launch(void* const* d_in, const int* in_sizes, int n_in,
                              void* d_out, int out_size)
{
    const float* query = (const float*)d_in[0];
    const float* key   = (const float*)d_in[1];
    const float* value = (const float*)d_in[2];
    const float* w_q   = (const float*)d_in[3];
    const float* b_q   = (const float*)d_in[4];
    const float* w_k   = (const float*)d_in[5];
    const float* b_k   = (const float*)d_in[6];
    const float* w_v   = (const float*)d_in[7];
    const float* b_v   = (const float*)d_in[8];
    const float* w_o   = (const float*)d_in[9];
    const float* b_o   = (const float*)d_in[10];
    float* out = (float*)d_out;

    uint16_t *ah, *al, *wh, *wl, *qh, *ql, *kh, *kl, *vh, *vl, *oh, *ol;
    cudaGetSymbolAddress((void**)&ah, g_ah);
    cudaGetSymbolAddress((void**)&al, g_al);
    cudaGetSymbolAddress((void**)&wh, g_wh);
    cudaGetSymbolAddress((void**)&wl, g_wl);
    cudaGetSymbolAddress((void**)&qh, g_qh);
    cudaGetSymbolAddress((void**)&ql, g_ql);
    cudaGetSymbolAddress((void**)&kh, g_kh);
    cudaGetSymbolAddress((void**)&kl, g_kl);
    cudaGetSymbolAddress((void**)&vh, g_vh);
    cudaGetSymbolAddress((void**)&vl, g_vl);
    cudaGetSymbolAddress((void**)&oh, g_oh);
    cudaGetSymbolAddress((void**)&ol, g_ol);

    cudaFuncSetAttribute(gemm_bf16, cudaFuncAttributeMaxDynamicSharedMemorySize, GEMM_SMEM);
    cudaFuncSetAttribute(attn_tc, cudaFuncAttributeMaxDynamicSharedMemorySize, ATTN_SMEM);

    const int WN4 = TD * TD / 4;      // 262144
    const int AN4 = NTOK * TD / 4;    // 2097152

    // convert the four weight matrices
    conv_split<<<WN4 / 256, 256>>>((const float4*)w_q,
        (uint2*)(wh + 0 * TD * TD), (uint2*)(wl + 0 * TD * TD), WN4);
    conv_split<<<WN4 / 256, 256>>>((const float4*)w_k,
        (uint2*)(wh + 1 * TD * TD), (uint2*)(wl + 1 * TD * TD), WN4);
    conv_split<<<WN4 / 256, 256>>>((const float4*)w_v,
        (uint2*)(wh + 2 * TD * TD), (uint2*)(wl + 2 * TD * TD), WN4);
    conv_split<<<WN4 / 256, 256>>>((const float4*)w_o,
        (uint2*)(wh + 3 * TD * TD), (uint2*)(wl + 3 * TD * TD), WN4);

    dim3 gg(TD / 128, NTOK / 128);   // (8, 64)

    conv_split<<<AN4 / 256, 256>>>((const float4*)query, (uint2*)ah, (uint2*)al, AN4);
    gemm_bf16<<<gg, 256, GEMM_SMEM>>>(ah, al, wh + 0 * TD * TD, wl + 0 * TD * TD,
                                      b_q, QSCALE, qh, ql, nullptr, 0);
    conv_split<<<AN4 / 256, 256>>>((const float4*)key, (uint2*)ah, (uint2*)al, AN4);
    gemm_bf16<<<gg, 256, GEMM_SMEM>>>(ah, al, wh + 1 * TD * TD, wl + 1 * TD * TD,
                                      b_k, 1.0f, kh, kl, nullptr, 0);
    conv_split<<<AN4 / 256, 256>>>((const float4*)value, (uint2*)ah, (uint2*)al, AN4);
    gemm_bf16<<<gg, 256, GEMM_SMEM>>>(ah, al, wh + 2 * TD * TD, wl + 2 * TD * TD,
                                      b_v, 1.0f, vh, vl, nullptr, 0);

    attn_tc<<<dim3(TT / 128, TB * TH), 256, ATTN_SMEM>>>(qh, ql, kh, kl, vh, vl, oh, ol);

    gemm_bf16<<<gg, 256, GEMM_SMEM>>>(oh, ol, wh + 3 * TD * TD, wl + 3 * TD * TD,
                                      b_o, 1.0f, nullptr, nullptr, out, 1);
}

// round 6
// speedup vs baseline: 3.4303x; 1.0491x over previous
#include <cuda_runtime.h>
#include <cuda_bf16.h>
#include <cstdint>

// Problem constants
#define TB   4
#define TT   2048
#define TD   1024
#define TH   16
#define TDH  64
#define NTOK (TB * TT)          // 8192

#define QSCALE (0.125f * 1.44269504088896f)   // 1/sqrt(64) * log2(e)

// ---------------------------------------------------------------------------
// Scratch (device globals: allocation-free, graph-capture safe)  bf16 hi/lo
// ---------------------------------------------------------------------------
__device__ uint16_t g_ah[3][NTOK * TD], g_al[3][NTOK * TD];    // q/k/v input conversions
__device__ uint16_t g_wh[4 * TD * TD], g_wl[4 * TD * TD];      // W conversions
__device__ uint16_t g_qh[NTOK * TD], g_ql[NTOK * TD];          // [b][h][t][dh]
__device__ uint16_t g_kh[NTOK * TD], g_kl[NTOK * TD];
__device__ uint16_t g_vh[NTOK * TD], g_vl[NTOK * TD];
__device__ uint16_t g_oh[NTOK * TD], g_ol[NTOK * TD];          // attn out [n][d]

// ---------------------------------------------------------------------------
// helpers (compute_100-safe: sm_80+ features only)
// ---------------------------------------------------------------------------
__device__ __forceinline__ uint32_t smem_u32(const void* p) {
    uint32_t a;
    asm("{ .reg .u64 t; cvta.to.shared.u64 t, %1; cvt.u32.u64 %0, t; }"
        : "=r"(a) : "l"(p));
    return a;
}

#define LDMX4(r, addr) \
    asm volatile("ldmatrix.sync.aligned.m8n8.x4.shared.b16 {%0,%1,%2,%3}, [%4];" \
        : "=r"((r)[0]), "=r"((r)[1]), "=r"((r)[2]), "=r"((r)[3]) : "r"(addr))

#define LDMX4T(r, addr) \
    asm volatile("ldmatrix.sync.aligned.m8n8.x4.trans.shared.b16 {%0,%1,%2,%3}, [%4];" \
        : "=r"((r)[0]), "=r"((r)[1]), "=r"((r)[2]), "=r"((r)[3]) : "r"(addr))

#define LDMX2T(r, addr) \
    asm volatile("ldmatrix.sync.aligned.m8n8.x2.trans.shared.b16 {%0,%1}, [%2];" \
        : "=r"((r)[0]), "=r"((r)[1]) : "r"(addr))

#define MMA16816(d, a, b) \
    asm volatile("mma.sync.aligned.m16n8k16.row.col.f32.bf16.bf16.f32 " \
        "{%0,%1,%2,%3}, {%4,%5,%6,%7}, {%8,%9}, {%0,%1,%2,%3};" \
        : "+f"((d)[0]), "+f"((d)[1]), "+f"((d)[2]), "+f"((d)[3]) \
        : "r"((a)[0]), "r"((a)[1]), "r"((a)[2]), "r"((a)[3]), \
          "r"((b)[0]), "r"((b)[1]))

#define CP16(dst, src) \
    asm volatile("cp.async.cg.shared.global [%0], [%1], 16;" \
        :: "r"((uint32_t)(dst)), "l"(src))
#define CP_COMMIT() asm volatile("cp.async.commit_group;" ::: "memory")
#define CP_WAIT0()  asm volatile("cp.async.wait_group 0;" ::: "memory")

__device__ __forceinline__ float ex2(float x) {
    float y;
    asm("ex2.approx.f32 %0, %1;" : "=f"(y) : "f"(x));
    return y;
}

// split fp32 pair into packed bf16 hi / lo pairs (x -> low half)
__device__ __forceinline__ void split2(float x, float y, uint32_t& hi, uint32_t& lo) {
    __nv_bfloat16 hx = __float2bfloat16(x);
    __nv_bfloat16 hy = __float2bfloat16(y);
    float lx = x - __bfloat162float(hx);
    float ly = y - __bfloat162float(hy);
    __nv_bfloat162 H; H.x = hx; H.y = hy;
    __nv_bfloat162 L; L.x = __float2bfloat16(lx); L.y = __float2bfloat16(ly);
    hi = *reinterpret_cast<uint32_t*>(&H);
    lo = *reinterpret_cast<uint32_t*>(&L);
}

// ---------------------------------------------------------------------------
// conversion kernels: fp32 -> bf16 hi/lo  (fused: 4 weights / 3 inputs)
// ---------------------------------------------------------------------------
__global__ void conv_w(const float4* __restrict__ a, const float4* __restrict__ b,
                       const float4* __restrict__ c, const float4* __restrict__ d)
{
    int i = blockIdx.x * blockDim.x + threadIdx.x;
    int z = blockIdx.y;
    const float4* src = (z == 0) ? a : (z == 1) ? b : (z == 2) ? c : d;
    float4 v = src[i];
    uint32_t h0, l0, h1, l1;
    split2(v.x, v.y, h0, l0);
    split2(v.z, v.w, h1, l1);
    ((uint2*)(g_wh + (size_t)z * TD * TD))[i] = make_uint2(h0, h1);
    ((uint2*)(g_wl + (size_t)z * TD * TD))[i] = make_uint2(l0, l1);
}

__global__ void conv_in(const float4* __restrict__ a, const float4* __restrict__ b,
                        const float4* __restrict__ c)
{
    int i = blockIdx.x * blockDim.x + threadIdx.x;
    int z = blockIdx.y;
    const float4* src = (z == 0) ? a : (z == 1) ? b : c;
    float4 v = src[i];
    uint32_t h0, l0, h1, l1;
    split2(v.x, v.y, h0, l0);
    split2(v.z, v.w, h1, l1);
    ((uint2*)g_ah[z])[i] = make_uint2(h0, h1);
    ((uint2*)g_al[z])[i] = make_uint2(l0, l1);
}

// ---------------------------------------------------------------------------
// Tensor-core GEMM core (bf16x3), cp.async double-buffered, ONE sync/chunk.
// ---------------------------------------------------------------------------
#define BK 32
#define TSTRIDE 40
#define TILE_U16 (128 * TSTRIDE)
#define TILE_BYTES (TILE_U16 * 2)          // 10240
#define STAGE_BYTES (4 * TILE_BYTES)       // 40960
#define GEMM_SMEM (2 * STAGE_BYTES)        // 81920
#define NCHUNK (TD / BK)                   // 32

__device__ __forceinline__ void gemm_core(
    const uint16_t* __restrict__ Ah, const uint16_t* __restrict__ Al,
    const uint16_t* __restrict__ Wh, const uint16_t* __restrict__ Wl,
    const float* __restrict__ bias, float scale,
    uint16_t* __restrict__ Oh, uint16_t* __restrict__ Ol,
    float* __restrict__ Of, int mode, char* smem)
{
    const uint32_t sbase = smem_u32(smem);
    const int tid  = threadIdx.x;
    const int lane = tid & 31;
    const int wid  = tid >> 5;
    const int warp_m = wid & 3;
    const int warp_n = wid >> 2;
    const int mbase = blockIdx.y * 128;
    const int nbase = blockIdx.x * 128;

    const int a_mi   = lane >> 3;
    const int a_roff = ((a_mi & 1) << 3) + (lane & 7);
    const int a_koff = (a_mi >> 1) << 3;
    const int b_roff = (((lane >> 4) & 1) << 3) + (lane & 7);
    const int b_koff = ((lane >> 3) & 1) << 3;

    auto ISSUE = [&](int c) {
        uint32_t dst = sbase + (c & 1) * STAGE_BYTES;
        #pragma unroll
        for (int half = 0; half < 2; half++) {
            int id = tid + half * 256;
            int row = id >> 2, cq = id & 3;
            uint32_t so = dst + (uint32_t)(row * TSTRIDE + cq * 8) * 2;
            size_t goA = (size_t)(mbase + row) * TD + c * BK + cq * 8;
            size_t goW = (size_t)(nbase + row) * TD + c * BK + cq * 8;
            CP16(so,                  Ah + goA);
            CP16(so + TILE_BYTES,     Al + goA);
            CP16(so + 2 * TILE_BYTES, Wh + goW);
            CP16(so + 3 * TILE_BYTES, Wl + goW);
        }
    };

    float acc[2][8][4];
    #pragma unroll
    for (int mt = 0; mt < 2; mt++)
        #pragma unroll
        for (int nt = 0; nt < 8; nt++)
            #pragma unroll
            for (int r = 0; r < 4; r++) acc[mt][nt][r] = 0.0f;

    ISSUE(0);
    CP_COMMIT();

    for (int c = 0; c < NCHUNK; c++) {
        CP_WAIT0();
        __syncthreads();               // single barrier per chunk (orders buffer reuse)
        if (c < NCHUNK - 1) { ISSUE(c + 1); CP_COMMIT(); }

        const uint32_t sa = sbase + (c & 1) * STAGE_BYTES;
        const uint32_t sb = sa + 2 * TILE_BYTES;

        #pragma unroll
        for (int ks = 0; ks < 2; ks++) {
            const int k0 = ks * 16;
            uint32_t a_hi[2][4], a_lo[2][4];
            #pragma unroll
            for (int mt = 0; mt < 2; mt++) {
                int row = warp_m * 32 + mt * 16 + a_roff;
                uint32_t ad = sa + (uint32_t)(row * TSTRIDE + k0 + a_koff) * 2;
                LDMX4(a_hi[mt], ad);
                LDMX4(a_lo[mt], ad + TILE_BYTES);
            }
            #pragma unroll
            for (int ntp = 0; ntp < 4; ntp++) {
                int row = warp_n * 64 + ntp * 16 + b_roff;
                uint32_t bd = sb + (uint32_t)(row * TSTRIDE + k0 + b_koff) * 2;
                uint32_t bh[4], bl[4];
                LDMX4(bh, bd);
                LDMX4(bl, bd + TILE_BYTES);
                #pragma unroll
                for (int mt = 0; mt < 2; mt++) {
                    MMA16816(acc[mt][ntp * 2],     a_hi[mt], &bh[0]);
                    MMA16816(acc[mt][ntp * 2],     a_hi[mt], &bl[0]);
                    MMA16816(acc[mt][ntp * 2],     a_lo[mt], &bh[0]);
                    MMA16816(acc[mt][ntp * 2 + 1], a_hi[mt], &bh[2]);
                    MMA16816(acc[mt][ntp * 2 + 1], a_hi[mt], &bl[2]);
                    MMA16816(acc[mt][ntp * 2 + 1], a_lo[mt], &bh[2]);
                }
            }
        }
    }

    // epilogue
    const int gid = lane >> 2;
    const int tig = lane & 3;
    float2 bb[8];
    #pragma unroll
    for (int nt = 0; nt < 8; nt++)
        bb[nt] = *(const float2*)&bias[nbase + warp_n * 64 + nt * 8 + tig * 2];

    #pragma unroll
    for (int mt = 0; mt < 2; mt++) {
        #pragma unroll
        for (int half = 0; half < 2; half++) {
            int m = mbase + warp_m * 32 + mt * 16 + gid + half * 8;
            if (mode == 0) {
                int b = m >> 11;
                int t = m & (TT - 1);
                int h = (nbase + warp_n * 64) >> 6;
                size_t base = (((size_t)(b * TH + h)) * TT + t) * TDH;
                #pragma unroll
                for (int nt = 0; nt < 8; nt++) {
                    float vx = (acc[mt][nt][half * 2 + 0] + bb[nt].x) * scale;
                    float vy = (acc[mt][nt][half * 2 + 1] + bb[nt].y) * scale;
                    uint32_t hh, ll;
                    split2(vx, vy, hh, ll);
                    *(uint32_t*)(Oh + base + nt * 8 + tig * 2) = hh;
                    *(uint32_t*)(Ol + base + nt * 8 + tig * 2) = ll;
                }
            } else {
                float* op = Of + (size_t)m * TD + nbase + warp_n * 64;
                #pragma unroll
                for (int nt = 0; nt < 8; nt++) {
                    float2 v;
                    v.x = acc[mt][nt][half * 2 + 0] + bb[nt].x;
                    v.y = acc[mt][nt][half * 2 + 1] + bb[nt].y;
                    *(float2*)(op + nt * 8 + tig * 2) = v;
                }
            }
        }
    }
}

// fused QKV projections: grid (8, 64, 3)
__global__ __launch_bounds__(256, 2) void gemm_qkv(
    const float* __restrict__ b_q, const float* __restrict__ b_k,
    const float* __restrict__ b_v)
{
    extern __shared__ char smem[];
    const int z = blockIdx.z;
    const float* bias = (z == 0) ? b_q : (z == 1) ? b_k : b_v;
    uint16_t* oh = (z == 0) ? g_qh : (z == 1) ? g_kh : g_vh;
    uint16_t* ol = (z == 0) ? g_ql : (z == 1) ? g_kl : g_vl;
    gemm_core(g_ah[z], g_al[z], g_wh + (size_t)z * TD * TD, g_wl + (size_t)z * TD * TD,
              bias, (z == 0) ? QSCALE : 1.0f, oh, ol, nullptr, 0, smem);
}

// output projection: grid (8, 64)
__global__ __launch_bounds__(256, 2) void gemm_o(
    const float* __restrict__ b_o, float* __restrict__ out)
{
    extern __shared__ char smem[];
    gemm_core(g_oh, g_ol, g_wh + (size_t)3 * TD * TD, g_wl + (size_t)3 * TD * TD,
              b_o, 1.0f, nullptr, nullptr, out, 1, smem);
}

// ---------------------------------------------------------------------------
// Tensor-core flash attention (bf16x3), estimated-max softmax, MMA row-sums.
// Block = 128 queries x one (b,h); 8 warps (16 q-rows each); KV tile 64.
// smem (u16): QH[128][72], QL[128][72], 2 stages of {KH,KL,VH,VL}[64][72].
// V pad col 64 = 1.0 (ones column -> row sums via MMA).
// ---------------------------------------------------------------------------
#define SQ 72
#define OFF_QH 0
#define OFF_QL (128 * SQ)
#define KVBASE (2 * 128 * SQ)             // 18432
#define KVARR  (64 * SQ)                  // 4608
#define KVSTAGE (4 * KVARR)               // 18432
#define ATTN_SMEM ((KVBASE + 2 * KVSTAGE) * 2)   // 110592 bytes

__global__ __launch_bounds__(256, 2) void attn_tc()
{
    extern __shared__ uint16_t us[];
    const uint32_t sbase = smem_u32(us);
    const int tid  = threadIdx.x;
    const int lane = tid & 31;
    const int wid  = tid >> 5;
    const int bh = blockIdx.y;
    const int q0 = blockIdx.x * 128;

    const size_t bho = (size_t)bh * TT * TDH;
    const uint16_t* kp[4] = {g_kh + bho, g_kl + bho, g_vh + bho, g_vl + bho};

    const int a_mi   = lane >> 3;
    const int a_roff = ((a_mi & 1) << 3) + (lane & 7);
    const int a_koff = (a_mi >> 1) << 3;
    const int b_roff = (((lane >> 4) & 1) << 3) + (lane & 7);
    const int b_koff = ((lane >> 3) & 1) << 3;
    const int v_toff = (((lane >> 3) & 1) << 3) + (lane & 7);
    const int v_dhoff = (lane >> 4) << 3;
    const int gid = lane >> 2;
    const int tig = lane & 3;

    // Q tile cp.async loads
    #pragma unroll
    for (int i = 0; i < 8; i++) {
        const uint16_t* src = ((i < 4) ? g_qh : g_ql) + bho;
        int rid = ((i & 3) << 5) + (tid >> 3);
        int cq  = tid & 7;
        uint32_t dst = sbase +
            (uint32_t)(((i < 4) ? OFF_QH : OFF_QL) + rid * SQ + cq * 8) * 2;
        CP16(dst, src + (size_t)(q0 + rid) * TDH + cq * 8);
    }

    // init V pad columns (col 64 = 1.0 in VH; zeros elsewhere), both stages
    {
        int st = tid >> 7, arr = (tid >> 6) & 1, row = tid & 63;
        uint16_t* p = us + KVBASE + st * KVSTAGE + (2 + arr) * KVARR + row * SQ + 64;
        p[0] = (arr == 0) ? (uint16_t)0x3F80 : (uint16_t)0;
        #pragma unroll
        for (int j = 1; j < 8; j++) p[j] = 0;
    }

    auto ISSUE_KV = [&](int kt, int s) {
        uint32_t stb = sbase + (uint32_t)(KVBASE + s * KVSTAGE) * 2;
        #pragma unroll
        for (int i = 0; i < 8; i++) {
            const int arr = i >> 1;
            int rid = ((i & 1) << 5) + (tid >> 3);
            int cq  = tid & 7;
            uint32_t dst = stb + (uint32_t)(arr * KVARR + rid * SQ + cq * 8) * 2;
            CP16(dst, kp[arr] + (size_t)(kt + rid) * TDH + cq * 8);
        }
    };

    ISSUE_KV(0, 0);
    CP_COMMIT();

    float oacc[8][4], osum[4];
    #pragma unroll
    for (int nt = 0; nt < 8; nt++)
        #pragma unroll
        for (int r = 0; r < 4; r++) oacc[nt][r] = 0.0f;
    #pragma unroll
    for (int r = 0; r < 4; r++) osum[r] = 0.0f;
    float mrow0 = 0.0f, mrow1 = 0.0f;   // estimated max (base-2 units)

    const int NKV = TT / 64;
    for (int ti = 0; ti < NKV; ti++) {
        CP_WAIT0();
        __syncthreads();
        if (ti < NKV - 1) { ISSUE_KV((ti + 1) * 64, (ti + 1) & 1); CP_COMMIT(); }

        const uint32_t kb = (uint32_t)(KVBASE + (ti & 1) * KVSTAGE);

        // ---- S = Q K^T (Q pre-scaled by log2e/8) ----
        float sacc[8][4];
        #pragma unroll
        for (int nt = 0; nt < 8; nt++)
            #pragma unroll
            for (int r = 0; r < 4; r++) sacc[nt][r] = 0.0f;

        #pragma unroll
        for (int ks = 0; ks < 4; ks++) {
            const int k0 = ks * 16;
            uint32_t ah[4], alr[4];
            {
                uint32_t ad = sbase + (uint32_t)((wid * 16 + a_roff) * SQ + k0 + a_koff) * 2;
                LDMX4(ah,  ad + OFF_QH * 2);
                LDMX4(alr, ad + OFF_QL * 2);
            }
            #pragma unroll
            for (int np = 0; np < 4; np++) {
                uint32_t bd = sbase +
                    (uint32_t)(kb + (np * 16 + b_roff) * SQ + k0 + b_koff) * 2;
                uint32_t bh[4], bl[4];
                LDMX4(bh, bd);
                LDMX4(bl, bd + KVARR * 2);
                MMA16816(sacc[np * 2],     ah,  &bh[0]);
                MMA16816(sacc[np * 2],     ah,  &bl[0]);
                MMA16816(sacc[np * 2],     alr, &bh[0]);
                MMA16816(sacc[np * 2 + 1], ah,  &bh[2]);
                MMA16816(sacc[np * 2 + 1], ah,  &bl[2]);
                MMA16816(sacc[np * 2 + 1], alr, &bh[2]);
            }
        }

        // ---- exp with ESTIMATED max (mrow from previous tiles); track local max ----
        float mx0 = -1e30f, mx1 = -1e30f;
        #pragma unroll
        for (int nt = 0; nt < 8; nt++) {
            mx0 = fmaxf(mx0, fmaxf(sacc[nt][0], sacc[nt][1]));
            mx1 = fmaxf(mx1, fmaxf(sacc[nt][2], sacc[nt][3]));
            sacc[nt][0] = ex2(sacc[nt][0] - mrow0);
            sacc[nt][1] = ex2(sacc[nt][1] - mrow0);
            sacc[nt][2] = ex2(sacc[nt][2] - mrow1);
            sacc[nt][3] = ex2(sacc[nt][3] - mrow1);
        }

        // ---- O' += P' V  (unrescaled; ones column accumulates row sums) ----
        #pragma unroll
        for (int kc = 0; kc < 4; kc++) {
            uint32_t pah[4], pal[4];
            split2(sacc[2 * kc][0],     sacc[2 * kc][1],     pah[0], pal[0]);
            split2(sacc[2 * kc][2],     sacc[2 * kc][3],     pah[1], pal[1]);
            split2(sacc[2 * kc + 1][0], sacc[2 * kc + 1][1], pah[2], pal[2]);
            split2(sacc[2 * kc + 1][2], sacc[2 * kc + 1][3], pah[3], pal[3]);
            // ones-column (V pad col 64) -> row sums
            {
                uint32_t od = sbase +
                    (uint32_t)(kb + 2 * KVARR + (kc * 16 + (lane & 15)) * SQ + 64) * 2;
                uint32_t ones[2];
                LDMX2T(ones, od);
                MMA16816(osum, pah, ones);
                MMA16816(osum, pal, ones);
            }
            #pragma unroll
            for (int np = 0; np < 4; np++) {
                uint32_t vd = sbase +
                    (uint32_t)(kb + 2 * KVARR + (kc * 16 + v_toff) * SQ + np * 16 + v_dhoff) * 2;
                uint32_t bh[4], bl[4];
                LDMX4T(bh, vd);
                LDMX4T(bl, vd + KVARR * 2);
                MMA16816(oacc[np * 2],     pah, &bh[0]);
                MMA16816(oacc[np * 2],     pah, &bl[0]);
                MMA16816(oacc[np * 2],     pal, &bh[0]);
                MMA16816(oacc[np * 2 + 1], pah, &bh[2]);
                MMA16816(oacc[np * 2 + 1], pah, &bl[2]);
                MMA16816(oacc[np * 2 + 1], pal, &bh[2]);
            }
        }

        // ---- max reduction + rescale (overlaps PV tensor work) ----
        mx0 = fmaxf(mx0, __shfl_xor_sync(0xffffffffu, mx0, 1));
        mx0 = fmaxf(mx0, __shfl_xor_sync(0xffffffffu, mx0, 2));
        mx1 = fmaxf(mx1, __shfl_xor_sync(0xffffffffu, mx1, 1));
        mx1 = fmaxf(mx1, __shfl_xor_sync(0xffffffffu, mx1, 2));
        float mn0 = fmaxf(mrow0, mx0);
        float mn1 = fmaxf(mrow1, mx1);
        float al0 = ex2(mrow0 - mn0);
        float al1 = ex2(mrow1 - mn1);
        mrow0 = mn0; mrow1 = mn1;
        #pragma unroll
        for (int nt = 0; nt < 8; nt++) {
            oacc[nt][0] *= al0; oacc[nt][1] *= al0;
            oacc[nt][2] *= al1; oacc[nt][3] *= al1;
        }
        osum[0] *= al0; osum[1] *= al0;
        osum[2] *= al1; osum[3] *= al1;
    }

    // ---- epilogue: normalize by MMA-computed row sums, split, write hi/lo ----
    const int b = bh >> 4;
    const int h = bh & 15;
    float rs0 = __shfl_sync(0xffffffffu, osum[0], lane & 28);
    float rs1 = __shfl_sync(0xffffffffu, osum[2], lane & 28);
    const float inv0 = 1.0f / rs0;
    const float inv1 = 1.0f / rs1;
    #pragma unroll
    for (int half = 0; half < 2; half++) {
        int t = q0 + wid * 16 + gid + half * 8;
        float inv = half ? inv1 : inv0;
        size_t n = (size_t)b * TT + t;
        size_t base = n * TD + h * TDH;
        #pragma unroll
        for (int nt = 0; nt < 8; nt++) {
            float vx = oacc[nt][half * 2 + 0] * inv;
            float vy = oacc[nt][half * 2 + 1] * inv;
            uint32_t hh, ll;
            split2(vx, vy, hh, ll);
            *(uint32_t*)(g_oh + base + nt * 8 + tig * 2) = hh;
            *(uint32_t*)(g_ol + base + nt * 8 + tig * 2) = ll;
        }
    }
}

// ---------------------------------------------------------------------------
// Launch
// ---------------------------------------------------------------------------
extern "C" void kernel_launch(void* const* d_in, const int* in_sizes, int n_in,
                              void* d_out, int out_size)
{
    const float* query = (const float*)d_in[0];
    const float* key   = (const float*)d_in[1];
    const float* value = (const float*)d_in[2];
    const float* b_q   = (const float*)d_in[4];
    const float* b_k   = (const float*)d_in[6];
    const float* b_v   = (const float*)d_in[8];
    const float* w_q   = (const float*)d_in[3];
    const float* w_k   = (const float*)d_in[5];
    const float* w_v   = (const float*)d_in[7];
    const float* w_o   = (const float*)d_in[9];
    const float* b_o   = (const float*)d_in[10];
    float* out = (float*)d_out;

    cudaFuncSetAttribute(gemm_qkv, cudaFuncAttributeMaxDynamicSharedMemorySize, GEMM_SMEM);
    cudaFuncSetAttribute(gemm_o,   cudaFuncAttributeMaxDynamicSharedMemorySize, GEMM_SMEM);
    cudaFuncSetAttribute(attn_tc,  cudaFuncAttributeMaxDynamicSharedMemorySize, ATTN_SMEM);

    const int WN4 = TD * TD / 4;      // 262144
    const int AN4 = NTOK * TD / 4;    // 2097152

    conv_w<<<dim3(WN4 / 256, 4), 256>>>((const float4*)w_q, (const float4*)w_k,
                                        (const float4*)w_v, (const float4*)w_o);
    conv_in<<<dim3(AN4 / 256, 3), 256>>>((const float4*)query, (const float4*)key,
                                         (const float4*)value);

    gemm_qkv<<<dim3(TD / 128, NTOK / 128, 3), 256, GEMM_SMEM>>>(b_q, b_k, b_v);

    attn_tc<<<dim3(TT / 128, TB * TH), 256, ATTN_SMEM>>>();

    gemm_o<<<dim3(TD / 128, NTOK / 128), 256, GEMM_SMEM>>>(b_o, out);
}